// round 3
// baseline (speedup 1.0000x reference)
#include <cuda_runtime.h>
#include <math.h>

// ---------------- problem constants ----------------
#define SEQ    2000
#define NSEQ   8            // B*C
#define NROWS  (NSEQ*SEQ)   // 16000
#define DM     256
#define NH     8
#define KD     32
#define CH     500
#define NC     4
#define SCALING 0.17677669529663689f   // 32^-0.5

// ---------------- scratch (device globals; no allocations) ----------------
__device__ float g_xn  [NROWS*DM];
__device__ float g_q   [NROWS*DM];
__device__ float g_k   [NROWS*DM];
__device__ float g_v   [NROWS*DM];
__device__ float g_g   [NROWS*DM];
__device__ float g_gate[NROWS*DM];
__device__ float g_x1  [NROWS*DM];
__device__ float g_yn  [NROWS*DM];
__device__ float g_qkv [NROWS*768];
__device__ float g_attn[NROWS*DM];
__device__ float g_kv   [256*KD*KD];
__device__ float g_state[256*KD*KD];
__device__ float g_cs   [256];

__device__ __forceinline__ float head_decay(int h) {
    return log1pf(-exp2f(-5.0f - (float)h));   // log(1 - 2^{-5-h})
}

__device__ __forceinline__ float warp_sum(float v) {
    v += __shfl_xor_sync(0xffffffffu, v, 16);
    v += __shfl_xor_sync(0xffffffffu, v, 8);
    v += __shfl_xor_sync(0xffffffffu, v, 4);
    v += __shfl_xor_sync(0xffffffffu, v, 2);
    v += __shfl_xor_sync(0xffffffffu, v, 1);
    return v;
}

// row permutation between (b,c,t) storage and (b,t,c) logical order
__device__ __forceinline__ int perm_row(int lr) {
    int b = lr / (SEQ*4);
    int rem = lr - b*(SEQ*4);
    int t = rem >> 2;
    int c = rem & 3;
    return (b*4 + c)*SEQ + t;
}

// ---------------- layernorm: one warp per row of 256 ----------------
__global__ __launch_bounds__(256) void ln_kernel(
    const float* __restrict__ src, float* __restrict__ dst,
    const float* __restrict__ gw, const float* __restrict__ bw, int permute)
{
    int row  = blockIdx.x*8 + (threadIdx.x >> 5);
    int lane = threadIdx.x & 31;
    int srow = permute ? perm_row(row) : row;

    const float* p = src + (size_t)srow*DM;
    float vals[8];
    float s = 0.f;
#pragma unroll
    for (int j = 0; j < 8; j++) { vals[j] = p[lane + 32*j]; s += vals[j]; }
    s = warp_sum(s);
    float mean = s * (1.f/256.f);
    float vs = 0.f;
#pragma unroll
    for (int j = 0; j < 8; j++) { float d = vals[j]-mean; vs += d*d; }
    vs = warp_sum(vs);
    float inv = rsqrtf(vs*(1.f/256.f) + 1e-5f);
    float* q = dst + (size_t)row*DM;
#pragma unroll
    for (int j = 0; j < 8; j++) {
        int col = lane + 32*j;
        q[col] = (vals[j]-mean)*inv*gw[col] + bw[col];
    }
}

// ---------------- generic fp32 GEMM: C[M,N] = A[M,K] @ W[N,K]^T ----------------
// alpha scale, optional bias[N], optional residual (row-permuted if permute),
// C written (row-permuted if permute). Requires M%128==0, N%128==0, K%16==0.
#define BM 128
#define BN 128
#define BK 16
__global__ __launch_bounds__(256) void gemm_nt(
    const float* __restrict__ A, const float* __restrict__ W,
    const float* __restrict__ bias, const float* __restrict__ res,
    float* __restrict__ C, int M, int N, int K, float alpha, int permute)
{
    __shared__ float As[BK][BM+4];
    __shared__ float Bs[BK][BN+4];
    int tid  = threadIdx.x;
    int row0 = blockIdx.x * BM;
    int col0 = blockIdx.y * BN;
    int tx = tid & 15, ty = tid >> 4;

    float acc[8][8];
#pragma unroll
    for (int i = 0; i < 8; i++)
#pragma unroll
        for (int j = 0; j < 8; j++) acc[i][j] = 0.f;

    for (int k0 = 0; k0 < K; k0 += BK) {
#pragma unroll
        for (int u = 0; u < 2; u++) {
            int idx = tid*2 + u;         // 0..511
            int m  = idx >> 2;
            int kq = idx & 3;
            float4 av = *(const float4*)(A + (size_t)(row0+m)*K + k0 + kq*4);
            As[kq*4+0][m] = av.x; As[kq*4+1][m] = av.y;
            As[kq*4+2][m] = av.z; As[kq*4+3][m] = av.w;
            float4 bv = *(const float4*)(W + (size_t)(col0+m)*K + k0 + kq*4);
            Bs[kq*4+0][m] = bv.x; Bs[kq*4+1][m] = bv.y;
            Bs[kq*4+2][m] = bv.z; Bs[kq*4+3][m] = bv.w;
        }
        __syncthreads();
#pragma unroll
        for (int kk = 0; kk < BK; kk++) {
            float4 a0 = *(const float4*)&As[kk][ty*8];
            float4 a1 = *(const float4*)&As[kk][ty*8+4];
            float4 b0 = *(const float4*)&Bs[kk][tx*8];
            float4 b1 = *(const float4*)&Bs[kk][tx*8+4];
            float a[8] = {a0.x,a0.y,a0.z,a0.w,a1.x,a1.y,a1.z,a1.w};
            float b[8] = {b0.x,b0.y,b0.z,b0.w,b1.x,b1.y,b1.z,b1.w};
#pragma unroll
            for (int i = 0; i < 8; i++)
#pragma unroll
                for (int j = 0; j < 8; j++) acc[i][j] += a[i]*b[j];
        }
        __syncthreads();
    }

#pragma unroll
    for (int i = 0; i < 8; i++) {
        int gr = row0 + ty*8 + i;
        int pr = permute ? perm_row(gr) : gr;
        const float* rrow = res ? res + (size_t)pr*N : nullptr;
        float* crow = C + (size_t)pr*N;
#pragma unroll
        for (int j = 0; j < 8; j++) {
            int gc = col0 + tx*8 + j;
            float v = acc[i][j]*alpha;
            if (bias) v += bias[gc];
            if (rrow) v += rrow[gc];
            crow[gc] = v;
        }
    }
}

// ---------------- rotary (theta shift), in-place ----------------
__global__ __launch_bounds__(256) void rotary_kernel(float* __restrict__ X)
{
    int p = blockIdx.x*256 + threadIdx.x;       // pair index
    if (p >= NROWS*128) return;
    int row = p >> 7;
    int w   = p & 127;          // h*16 + pj
    int pj  = w & 15;
    int t   = row % SEQ;        // absolute position within sequence
    float angle = expf(-(float)pj * 0.61402269158f);  // 10000^{-pj/15}
    float sn, cn;
    sincosf((float)t * angle, &sn, &cn);
    size_t off = (size_t)row*DM + (size_t)w*2;
    float x1 = X[off], x2 = X[off+1];
    X[off]   = x1*cn - x2*sn;
    X[off+1] = x2*cn + x1*sn;
}

// ---------------- per-chunk kv = kr^T @ (v * vdec)  (32x32) ----------------
__global__ __launch_bounds__(256) void kv_kernel()
{
    int blk = blockIdx.x;           // b*32 + n*8 + h
    int h = blk & 7, n = (blk>>3)&3, b = blk>>5;
    int base = b*SEQ + n*CH;
    int colh = h*KD;
    float decay = head_decay(h);
    float lrs   = expm1f(500.f*decay)/expm1f(decay);   // last_row_sum

    __shared__ float Ks[32][33];
    __shared__ float Vs[32][33];
    int tid = threadIdx.x;
    int d  = tid & 31;
    int kq = tid >> 5;              // 0..7 -> rows kq*4..kq*4+3
    float acc[4] = {0.f,0.f,0.f,0.f};

    for (int jt = 0; jt < 16; jt++) {
        for (int e = tid; e < 1024; e += 256) {
            int jj = e >> 5, c = e & 31;
            int j = jt*32 + jj;
            float kk_ = 0.f, vv_ = 0.f;
            if (j < CH) {
                kk_ = g_k[(size_t)(base+j)*DM + colh + c];
                float vdec = expf(decay*(499.f - (float)j)) / lrs;
                vv_ = g_v[(size_t)(base+j)*DM + colh + c] * vdec;
            }
            Ks[jj][c] = kk_;
            Vs[jj][c] = vv_;
        }
        __syncthreads();
#pragma unroll 8
        for (int jj = 0; jj < 32; jj++) {
            float vv = Vs[jj][d];
#pragma unroll
            for (int i = 0; i < 4; i++)
                acc[i] += Ks[jj][kq*4+i] * vv;
        }
        __syncthreads();
    }
#pragma unroll
    for (int i = 0; i < 4; i++)
        g_kv[(size_t)blk*1024 + (kq*4+i)*32 + d] = acc[i];
}

// ---------------- sequential scan over chunks per (b,h) ----------------
__global__ __launch_bounds__(256) void scan_kernel()
{
    int bh = blockIdx.x;            // b*8 + h
    int b = bh >> 3, h = bh & 7;
    float decay = head_decay(h);
    float cross_decay = expf(decay * 500.f);
    int tid = threadIdx.x;
    int d  = tid & 31;
    int kq = tid >> 5;
    float st[4] = {0.f,0.f,0.f,0.f};
    float cs = 1.f;
    __shared__ float part[8][32];
    __shared__ float csh;

    for (int n = 0; n < NC; n++) {
        int idx = b*32 + n*8 + h;
#pragma unroll
        for (int i = 0; i < 4; i++)
            g_state[(size_t)idx*1024 + (kq*4+i)*32 + d] = st[i];
        if (tid == 0) g_cs[idx] = cs;
        float colp = 0.f;
#pragma unroll
        for (int i = 0; i < 4; i++) {
            st[i] = st[i]*cross_decay + g_kv[(size_t)idx*1024 + (kq*4+i)*32 + d];
            colp += fabsf(st[i]);
        }
        part[kq][d] = colp;
        __syncthreads();
        if (tid < 32) {
            float c = 0.f;
#pragma unroll
            for (int q = 0; q < 8; q++) c += part[q][tid];
            for (int off = 16; off; off >>= 1)
                c = fmaxf(c, __shfl_xor_sync(0xffffffffu, c, off));
            if (tid == 0) csh = fmaxf(c, 1.f);
        }
        __syncthreads();
        cs = csh;
    }
}

// ---------------- fused retention inner + cross + RMS + gate ----------------
// one block per (b,n,h); 256 threads = 8 warps; lane = head-dim / column
__global__ __launch_bounds__(256) void retention_inner()
{
    int blk = blockIdx.x;           // b*32 + n*8 + h
    int h = blk & 7, n = (blk>>3)&3, b = blk>>5;
    int base = b*SEQ + n*CH;
    int colh = h*KD;
    float decay = head_decay(h);
    float lrs   = expm1f(500.f*decay)/expm1f(decay);
    float cs    = g_cs[blk];

    __shared__ float Qst[32][68];   // k-major Q tile (k, row)
    __shared__ float Kst[32][36];   // k-major K tile (k, jj)
    __shared__ float Vs [32][33];   // (jj, d)
    __shared__ float Sst[32][68];   // (jj, row)
    __shared__ float KVs[32][33];   // (k, d)
    __shared__ float rowFac[64], qFac[64], jFac[32];
    __shared__ float rowPart[4][64];

    int tid  = threadIdx.x;
    int warp = tid >> 5;
    int lane = tid & 31;

    // load kv state
#pragma unroll
    for (int i = 0; i < 4; i++) {
        int e = tid*4 + i;
        KVs[e >> 5][e & 31] = g_state[(size_t)blk*1024 + e];
    }

    for (int it = 0; it < 8; it++) {
        int ibase = it*64;
        // load Q tile (transposed) + per-row factors, zero rowPart
        for (int e = tid; e < 64*32; e += 256) {
            int rr = e >> 5, k = e & 31;
            int i = ibase + rr;
            Qst[k][rr] = (i < CH) ? g_q[(size_t)(base+i)*DM + colh + k] : 0.f;
        }
        if (tid < 64) {
            int i = ibase + tid;
            if (i < CH) {
                float scale = sqrtf(expm1f(decay*(float)(i+1)) / expm1f(decay));
                rowFac[tid] = expf(decay*(float)i) / scale;
                qFac[tid]   = expf(decay*(float)(i+1)) * lrs / scale;
            } else { rowFac[tid] = 0.f; qFac[tid] = 0.f; }
        }
        ((float*)rowPart)[tid] = 0.f;
        __syncthreads();

        float O[8];
#pragma unroll
        for (int u = 0; u < 8; u++) O[u] = 0.f;

        int maxi = ibase + 63; if (maxi > CH-1) maxi = CH-1;
        int jtiles = maxi/32 + 1;

        for (int jt = 0; jt < jtiles; jt++) {
            int jbase = jt*32;
            // load K (transposed), V, jFac
            for (int e = tid; e < 1024; e += 256) {
                int jj = e >> 5, k = e & 31;
                int j = jbase + jj;
                float kk_ = 0.f, vv_ = 0.f;
                if (j < CH) {
                    kk_ = g_k[(size_t)(base+j)*DM + colh + k];
                    vv_ = g_v[(size_t)(base+j)*DM + colh + k];
                }
                Kst[k][jj] = kk_;
                Vs[jj][k]  = vv_;
            }
            if (tid < 32) {
                int j = jbase + tid;
                jFac[tid] = (j < CH) ? expf(-decay*(float)j) : 0.f;
            }
            __syncthreads();

            // stage 1: S = Q K^T * mask ; thread -> row r=(warp&1)*32+lane, 8 jj's
            {
                int r  = ((warp & 1) << 5) + lane;
                int i  = ibase + r;
                int jb = (warp >> 1) * 8;
                float s[8];
#pragma unroll
                for (int u = 0; u < 8; u++) s[u] = 0.f;
#pragma unroll
                for (int k = 0; k < 32; k++) {
                    float qv = Qst[k][r];
                    float4 b0 = *(const float4*)&Kst[k][jb];
                    float4 b1 = *(const float4*)&Kst[k][jb+4];
                    s[0] += qv*b0.x; s[1] += qv*b0.y; s[2] += qv*b0.z; s[3] += qv*b0.w;
                    s[4] += qv*b1.x; s[5] += qv*b1.y; s[6] += qv*b1.z; s[7] += qv*b1.w;
                }
                float rf = rowFac[r];
                float part = 0.f;
#pragma unroll
                for (int u = 0; u < 8; u++) {
                    int j = jbase + jb + u;
                    float sv = s[u] * rf * jFac[jb+u];
                    if (j > i) sv = 0.f;
                    Sst[jb+u][r] = sv;
                    part += fabsf(sv);
                }
                rowPart[warp >> 1][r] += part;
            }
            __syncthreads();

            // stage 2: O += S V ; thread -> rows warp*8..+7, col=lane
#pragma unroll 8
            for (int jj = 0; jj < 32; jj++) {
                float4 a0 = *(const float4*)&Sst[jj][warp*8];
                float4 a1 = *(const float4*)&Sst[jj][warp*8+4];
                float vv = Vs[jj][lane];
                O[0] += a0.x*vv; O[1] += a0.y*vv; O[2] += a0.z*vv; O[3] += a0.w*vv;
                O[4] += a1.x*vv; O[5] += a1.y*vv; O[6] += a1.z*vv; O[7] += a1.w*vv;
            }
            __syncthreads();
        }

        // cross term: Cacc = Q @ KVstate
        float Cacc[8];
#pragma unroll
        for (int u = 0; u < 8; u++) Cacc[u] = 0.f;
#pragma unroll
        for (int k = 0; k < 32; k++) {
            float4 a0 = *(const float4*)&Qst[k][warp*8];
            float4 a1 = *(const float4*)&Qst[k][warp*8+4];
            float kvv = KVs[k][lane];
            Cacc[0] += a0.x*kvv; Cacc[1] += a0.y*kvv; Cacc[2] += a0.z*kvv; Cacc[3] += a0.w*kvv;
            Cacc[4] += a1.x*kvv; Cacc[5] += a1.y*kvv; Cacc[6] += a1.z*kvv; Cacc[7] += a1.w*kvv;
        }

        // epilogue: normalize, RMS over head dim, silu gate, store
#pragma unroll
        for (int u = 0; u < 8; u++) {
            int rr = warp*8 + u;
            int i  = ibase + rr;
            if (i < CH) {
                float rowsum = rowPart[0][rr] + rowPart[1][rr]
                             + rowPart[2][rr] + rowPart[3][rr];
                float iscale = fmaxf(rowsum, 1.f);
                float ascale = fmaxf(iscale, cs);
                float val = (O[u] + qFac[rr]*Cacc[u]) / ascale;
                float sq = warp_sum(val*val);
                val *= rsqrtf(sq*(1.f/32.f) + 1e-6f);
                size_t grow = (size_t)(base + i);
                float gv = g_g[grow*DM + colh + lane];
                float gate = gv / (1.f + expf(-gv));     // silu
                g_gate[grow*DM + colh + lane] = gate * val;
            }
        }
        __syncthreads();
    }
}

// ---------------- tiny MHA over seq=4 ; block per (b,t), warp per head ----------------
__global__ __launch_bounds__(256) void mha_kernel()
{
    int bt = blockIdx.x;            // 0..3999
    int h    = threadIdx.x >> 5;
    int lane = threadIdx.x & 31;
    size_t r0 = (size_t)bt * 4;
    float q[4], k[4], v[4];
#pragma unroll
    for (int c = 0; c < 4; c++) {
        size_t off = (r0 + c)*768 + h*KD + lane;
        q[c] = g_qkv[off] * SCALING;
        k[c] = g_qkv[off + 256];
        v[c] = g_qkv[off + 512];
    }
    float s[4][4];
#pragma unroll
    for (int i = 0; i < 4; i++)
#pragma unroll
        for (int j = 0; j < 4; j++)
            s[i][j] = warp_sum(q[i]*k[j]);
#pragma unroll
    for (int i = 0; i < 4; i++) {
        float m = fmaxf(fmaxf(s[i][0], s[i][1]), fmaxf(s[i][2], s[i][3]));
        float e0 = expf(s[i][0]-m), e1 = expf(s[i][1]-m),
              e2 = expf(s[i][2]-m), e3 = expf(s[i][3]-m);
        float inv = 1.f/(e0+e1+e2+e3);
        float o = (e0*v[0] + e1*v[1] + e2*v[2] + e3*v[3]) * inv;
        g_attn[(r0+i)*DM + h*KD + lane] = o;
    }
}

// ---------------- launcher ----------------
extern "C" void kernel_launch(void* const* d_in, const int* in_sizes, int n_in,
                              void* d_out, int out_size)
{
    const float* x    = (const float*)d_in[0];
    const float* ln1g = (const float*)d_in[1];
    const float* ln1b = (const float*)d_in[2];
    const float* ln2g = (const float*)d_in[3];
    const float* ln2b = (const float*)d_in[4];
    const float* qw   = (const float*)d_in[5];
    const float* kw   = (const float*)d_in[6];
    const float* vw   = (const float*)d_in[7];
    const float* gw   = (const float*)d_in[8];
    const float* ow   = (const float*)d_in[9];
    const float* inw  = (const float*)d_in[10];
    const float* inb  = (const float*)d_in[11];
    const float* outw = (const float*)d_in[12];
    const float* outb = (const float*)d_in[13];
    float* out = (float*)d_out;

    float *p_xn, *p_q, *p_k, *p_v, *p_g, *p_gate, *p_x1, *p_yn, *p_qkv, *p_attn;
    cudaGetSymbolAddress((void**)&p_xn,   g_xn);
    cudaGetSymbolAddress((void**)&p_q,    g_q);
    cudaGetSymbolAddress((void**)&p_k,    g_k);
    cudaGetSymbolAddress((void**)&p_v,    g_v);
    cudaGetSymbolAddress((void**)&p_g,    g_g);
    cudaGetSymbolAddress((void**)&p_gate, g_gate);
    cudaGetSymbolAddress((void**)&p_x1,   g_x1);
    cudaGetSymbolAddress((void**)&p_yn,   g_yn);
    cudaGetSymbolAddress((void**)&p_qkv,  g_qkv);
    cudaGetSymbolAddress((void**)&p_attn, g_attn);

    dim3 g256(NROWS/BM, DM/BN);     // (125, 2)
    dim3 g768(NROWS/BM, 768/BN);    // (125, 6)

    // stage 1: retention
    ln_kernel<<<NROWS/8, 256>>>(x, p_xn, ln1g, ln1b, 0);
    gemm_nt<<<g256, 256>>>(p_xn, qw, nullptr, nullptr, p_q, NROWS, DM, DM, 1.f, 0);
    gemm_nt<<<g256, 256>>>(p_xn, kw, nullptr, nullptr, p_k, NROWS, DM, DM, SCALING, 0);
    gemm_nt<<<g256, 256>>>(p_xn, vw, nullptr, nullptr, p_v, NROWS, DM, DM, 1.f, 0);
    gemm_nt<<<g256, 256>>>(p_xn, gw, nullptr, nullptr, p_g, NROWS, DM, DM, 1.f, 0);
    rotary_kernel<<<NROWS*128/256, 256>>>(p_q);
    rotary_kernel<<<NROWS*128/256, 256>>>(p_k);
    kv_kernel<<<256, 256>>>();
    scan_kernel<<<64, 256>>>();
    retention_inner<<<256, 256>>>();
    gemm_nt<<<g256, 256>>>(p_gate, ow, nullptr, x, p_x1, NROWS, DM, DM, 1.f, 0);

    // stage 2: MHA over chunk axis (permuted rows)
    ln_kernel<<<NROWS/8, 256>>>(p_x1, p_yn, ln2g, ln2b, 1);
    gemm_nt<<<g768, 256>>>(p_yn, inw, inb, nullptr, p_qkv, NROWS, 768, DM, 1.f, 0);
    mha_kernel<<<NROWS/4, 256>>>();
    gemm_nt<<<g256, 256>>>(p_attn, outw, outb, p_x1, out, NROWS, DM, DM, 1.f, 1);
}

// round 4
// speedup vs baseline: 1.7145x; 1.7145x over previous
#include <cuda_runtime.h>
#include <math.h>
#include <stdint.h>

// ---------------- problem constants ----------------
#define SEQ    2000
#define NSEQ   8            // B*C
#define NROWS  (NSEQ*SEQ)   // 16000
#define DM     256
#define NH     8
#define KD     32
#define CH     500
#define NC     4
#define SCALING 0.17677669529663689f   // 32^-0.5

// ---------------- scratch (device globals; no allocations) ----------------
__device__ float g_xn  [NROWS*DM];
__device__ float g_q   [NROWS*DM];
__device__ float g_k   [NROWS*DM];
__device__ float g_v   [NROWS*DM];
__device__ float g_g   [NROWS*DM];
__device__ float g_gate[NROWS*DM];
__device__ float g_x1  [NROWS*DM];
__device__ float g_yn  [NROWS*DM];
__device__ float g_qkv [NROWS*768];
__device__ float g_attn[NROWS*DM];
__device__ float g_kv   [256*KD*KD];
__device__ float g_state[256*KD*KD];
__device__ float g_cs   [256];

__device__ __forceinline__ float head_decay(int h) {
    return log1pf(-exp2f(-5.0f - (float)h));   // log(1 - 2^{-5-h})
}

__device__ __forceinline__ float warp_sum(float v) {
    v += __shfl_xor_sync(0xffffffffu, v, 16);
    v += __shfl_xor_sync(0xffffffffu, v, 8);
    v += __shfl_xor_sync(0xffffffffu, v, 4);
    v += __shfl_xor_sync(0xffffffffu, v, 2);
    v += __shfl_xor_sync(0xffffffffu, v, 1);
    return v;
}

// row permutation between (b,c,t) storage and (b,t,c) logical order
__device__ __forceinline__ int perm_row(int lr) {
    int b = lr / (SEQ*4);
    int rem = lr - b*(SEQ*4);
    int t = rem >> 2;
    int c = rem & 3;
    return (b*4 + c)*SEQ + t;
}

// ---------------- layernorm: one warp per row of 256 ----------------
__global__ __launch_bounds__(256) void ln_kernel(
    const float* __restrict__ src, float* __restrict__ dst,
    const float* __restrict__ gw, const float* __restrict__ bw, int permute)
{
    int row  = blockIdx.x*8 + (threadIdx.x >> 5);
    int lane = threadIdx.x & 31;
    int srow = permute ? perm_row(row) : row;

    const float* p = src + (size_t)srow*DM;
    float vals[8];
    float s = 0.f;
#pragma unroll
    for (int j = 0; j < 8; j++) { vals[j] = p[lane + 32*j]; s += vals[j]; }
    s = warp_sum(s);
    float mean = s * (1.f/256.f);
    float vs = 0.f;
#pragma unroll
    for (int j = 0; j < 8; j++) { float d = vals[j]-mean; vs += d*d; }
    vs = warp_sum(vs);
    float inv = rsqrtf(vs*(1.f/256.f) + 1e-5f);
    float* q = dst + (size_t)row*DM;
#pragma unroll
    for (int j = 0; j < 8; j++) {
        int col = lane + 32*j;
        q[col] = (vals[j]-mean)*inv*gw[col] + bw[col];
    }
}

// ================= tf32 tensor-core GEMM =================
// C[M,N] = A[M,K] @ W[N,K]^T ; tiles 128x128x32; 8 warps of 32x64.
// smem layout: [row][k] with row stride 36 words (conflict-free fragments).

__device__ __forceinline__ uint32_t f2tf32(float x) {
    uint32_t r; asm("cvt.rna.tf32.f32 %0, %1;" : "=r"(r) : "f"(x)); return r;
}

__device__ __forceinline__ void mma_tf32(float* d, const uint32_t* a,
                                         uint32_t b0, uint32_t b1) {
    asm volatile(
        "mma.sync.aligned.m16n8k8.row.col.f32.tf32.tf32.f32 "
        "{%0,%1,%2,%3}, {%4,%5,%6,%7}, {%8,%9}, {%0,%1,%2,%3};"
        : "+f"(d[0]), "+f"(d[1]), "+f"(d[2]), "+f"(d[3])
        : "r"(a[0]), "r"(a[1]), "r"(a[2]), "r"(a[3]), "r"(b0), "r"(b1));
}

__device__ __forceinline__ void gemm_tile(
    const float* __restrict__ A, const float* __restrict__ Wp, // Wp = W + col0*K
    const float* __restrict__ bias, const float* __restrict__ res,
    float* __restrict__ C, int K, int N, int row0, int col0,
    float alpha, int permute, uint32_t* As, uint32_t* Bs)
{
    int tid  = threadIdx.x;
    int warp = tid >> 5, lane = tid & 31;
    int wm = warp >> 1, wn = warp & 1;
    int gr = lane >> 2, gc = lane & 3;

    float acc[2][8][4];
#pragma unroll
    for (int mt = 0; mt < 2; mt++)
#pragma unroll
        for (int nt = 0; nt < 8; nt++)
#pragma unroll
            for (int u = 0; u < 4; u++) acc[mt][nt][u] = 0.f;

    float4 pa[4], pb[4];
#pragma unroll
    for (int u = 0; u < 4; u++) {
        int id = u*256 + tid;
        int m = id >> 3, kq = id & 7;
        pa[u] = *(const float4*)(A  + (size_t)(row0+m)*K + kq*4);
        pb[u] = *(const float4*)(Wp + (size_t)m*K       + kq*4);
    }

    int kblocks = K >> 5;
    for (int kb = 0; kb < kblocks; kb++) {
        __syncthreads();
#pragma unroll
        for (int u = 0; u < 4; u++) {
            int id = u*256 + tid;
            int m = id >> 3, kq = id & 7;
            uint4 av = make_uint4(f2tf32(pa[u].x), f2tf32(pa[u].y),
                                  f2tf32(pa[u].z), f2tf32(pa[u].w));
            uint4 bv = make_uint4(f2tf32(pb[u].x), f2tf32(pb[u].y),
                                  f2tf32(pb[u].z), f2tf32(pb[u].w));
            *(uint4*)&As[m*36 + kq*4] = av;
            *(uint4*)&Bs[m*36 + kq*4] = bv;
        }
        __syncthreads();
        if (kb + 1 < kblocks) {
            int koff = (kb+1)*32;
#pragma unroll
            for (int u = 0; u < 4; u++) {
                int id = u*256 + tid;
                int m = id >> 3, kq = id & 7;
                pa[u] = *(const float4*)(A  + (size_t)(row0+m)*K + koff + kq*4);
                pb[u] = *(const float4*)(Wp + (size_t)m*K       + koff + kq*4);
            }
        }
#pragma unroll
        for (int ks = 0; ks < 4; ks++) {
            int k0 = ks*8;
            uint32_t a[2][4];
#pragma unroll
            for (int mt = 0; mt < 2; mt++) {
                int base = (wm*32 + mt*16 + gr)*36 + k0 + gc;
                a[mt][0] = As[base];
                a[mt][1] = As[base + 288];     // +8 rows
                a[mt][2] = As[base + 4];
                a[mt][3] = As[base + 292];
            }
#pragma unroll
            for (int nt = 0; nt < 8; nt++) {
                int nb = (wn*64 + nt*8 + gr)*36 + k0 + gc;
                uint32_t b0 = Bs[nb], b1 = Bs[nb + 4];
                mma_tf32(acc[0][nt], a[0], b0, b1);
                mma_tf32(acc[1][nt], a[1], b0, b1);
            }
        }
    }

    // epilogue
#pragma unroll
    for (int mt = 0; mt < 2; mt++) {
#pragma unroll
        for (int h = 0; h < 2; h++) {
            int row = row0 + wm*32 + mt*16 + gr + h*8;
            int pr  = permute ? perm_row(row) : row;
            const float* rrow = res ? res + (size_t)pr*N : nullptr;
            float* crow = C + (size_t)pr*N;
#pragma unroll
            for (int nt = 0; nt < 8; nt++) {
                int c = col0 + wn*64 + nt*8 + gc*2;
                float v0 = acc[mt][nt][h*2+0] * alpha;
                float v1 = acc[mt][nt][h*2+1] * alpha;
                if (bias) { v0 += bias[c]; v1 += bias[c+1]; }
                if (rrow) { v0 += rrow[c]; v1 += rrow[c+1]; }
                *(float2*)&crow[c] = make_float2(v0, v1);
            }
        }
    }
}

__global__ __launch_bounds__(256) void gemm_nt(
    const float* __restrict__ A, const float* __restrict__ W,
    const float* __restrict__ bias, const float* __restrict__ res,
    float* __restrict__ C, int M, int N, int K, float alpha, int permute)
{
    __shared__ uint32_t As[128*36];
    __shared__ uint32_t Bs[128*36];
    int row0 = blockIdx.x * 128;
    int col0 = blockIdx.y * 128;
    gemm_tile(A, W + (size_t)col0*K, bias, res, C, K, N, row0, col0,
              alpha, permute, As, Bs);
}

// fused Q/K/V/G projections: grid (125, 8); y>>1 picks the weight, y&1 the col block
__global__ __launch_bounds__(256) void gemm_qkvg(const float* __restrict__ A,
    const float* __restrict__ qw, const float* __restrict__ kw,
    const float* __restrict__ vw, const float* __restrict__ gw)
{
    __shared__ uint32_t As[128*36];
    __shared__ uint32_t Bs[128*36];
    int w = blockIdx.y >> 1;
    int col0 = (blockIdx.y & 1) * 128;
    const float* W = (w == 0) ? qw : (w == 1) ? kw : (w == 2) ? vw : gw;
    float* C = (w == 0) ? g_q : (w == 1) ? g_k : (w == 2) ? g_v : g_g;
    float alpha = (w == 1) ? SCALING : 1.f;
    gemm_tile(A, W + (size_t)col0*DM, nullptr, nullptr, C, DM, DM,
              blockIdx.x*128, col0, alpha, 0, As, Bs);
}

// ---------------- rotary (theta shift), in-place ----------------
__global__ __launch_bounds__(256) void rotary_kernel(float* __restrict__ X)
{
    int p = blockIdx.x*256 + threadIdx.x;       // pair index
    if (p >= NROWS*128) return;
    int row = p >> 7;
    int w   = p & 127;          // h*16 + pj
    int pj  = w & 15;
    int t   = row % SEQ;        // absolute position within sequence
    float angle = expf(-(float)pj * 0.61402269158f);  // 10000^{-pj/15}
    float sn, cn;
    sincosf((float)t * angle, &sn, &cn);
    size_t off = (size_t)row*DM + (size_t)w*2;
    float x1 = X[off], x2 = X[off+1];
    X[off]   = x1*cn - x2*sn;
    X[off+1] = x2*cn + x1*sn;
}

// ---------------- per-chunk kv = kr^T @ (v * vdec)  (32x32) ----------------
__global__ __launch_bounds__(256) void kv_kernel()
{
    int blk = blockIdx.x;           // b*32 + n*8 + h
    int h = blk & 7, n = (blk>>3)&3, b = blk>>5;
    int base = b*SEQ + n*CH;
    int colh = h*KD;
    float decay = head_decay(h);
    float lrs   = expm1f(500.f*decay)/expm1f(decay);   // last_row_sum

    __shared__ float Ks[32][33];
    __shared__ float Vs[32][33];
    int tid = threadIdx.x;
    int d  = tid & 31;
    int kq = tid >> 5;              // 0..7 -> rows kq*4..kq*4+3
    float acc[4] = {0.f,0.f,0.f,0.f};

    for (int jt = 0; jt < 16; jt++) {
        for (int e = tid; e < 1024; e += 256) {
            int jj = e >> 5, c = e & 31;
            int j = jt*32 + jj;
            float kk_ = 0.f, vv_ = 0.f;
            if (j < CH) {
                kk_ = g_k[(size_t)(base+j)*DM + colh + c];
                float vdec = expf(decay*(499.f - (float)j)) / lrs;
                vv_ = g_v[(size_t)(base+j)*DM + colh + c] * vdec;
            }
            Ks[jj][c] = kk_;
            Vs[jj][c] = vv_;
        }
        __syncthreads();
#pragma unroll 8
        for (int jj = 0; jj < 32; jj++) {
            float vv = Vs[jj][d];
#pragma unroll
            for (int i = 0; i < 4; i++)
                acc[i] += Ks[jj][kq*4+i] * vv;
        }
        __syncthreads();
    }
#pragma unroll
    for (int i = 0; i < 4; i++)
        g_kv[(size_t)blk*1024 + (kq*4+i)*32 + d] = acc[i];
}

// ---------------- sequential scan over chunks per (b,h) ----------------
__global__ __launch_bounds__(256) void scan_kernel()
{
    int bh = blockIdx.x;            // b*8 + h
    int b = bh >> 3, h = bh & 7;
    float decay = head_decay(h);
    float cross_decay = expf(decay * 500.f);
    int tid = threadIdx.x;
    int d  = tid & 31;
    int kq = tid >> 5;
    float st[4] = {0.f,0.f,0.f,0.f};
    float cs = 1.f;
    __shared__ float part[8][32];
    __shared__ float csh;

    for (int n = 0; n < NC; n++) {
        int idx = b*32 + n*8 + h;
#pragma unroll
        for (int i = 0; i < 4; i++)
            g_state[(size_t)idx*1024 + (kq*4+i)*32 + d] = st[i];
        if (tid == 0) g_cs[idx] = cs;
        float colp = 0.f;
#pragma unroll
        for (int i = 0; i < 4; i++) {
            st[i] = st[i]*cross_decay + g_kv[(size_t)idx*1024 + (kq*4+i)*32 + d];
            colp += fabsf(st[i]);
        }
        part[kq][d] = colp;
        __syncthreads();
        if (tid < 32) {
            float c = 0.f;
#pragma unroll
            for (int q = 0; q < 8; q++) c += part[q][tid];
            for (int off = 16; off; off >>= 1)
                c = fmaxf(c, __shfl_xor_sync(0xffffffffu, c, off));
            if (tid == 0) csh = fmaxf(c, 1.f);
        }
        __syncthreads();
        cs = csh;
    }
}

// ---------------- fused retention inner + cross + RMS + gate ----------------
// one block per (b,n,h); 256 threads = 8 warps; lane = head-dim / column
__global__ __launch_bounds__(256) void retention_inner()
{
    int blk = blockIdx.x;           // b*32 + n*8 + h
    int h = blk & 7, n = (blk>>3)&3, b = blk>>5;
    int base = b*SEQ + n*CH;
    int colh = h*KD;
    float decay = head_decay(h);
    float lrs   = expm1f(500.f*decay)/expm1f(decay);
    float cs    = g_cs[blk];

    __shared__ float Qst[32][68];   // k-major Q tile (k, row)
    __shared__ float Kst[32][36];   // k-major K tile (k, jj)
    __shared__ float Vs [32][33];   // (jj, d)
    __shared__ float Sst[32][68];   // (jj, row)
    __shared__ float KVs[32][33];   // (k, d)
    __shared__ float rowFac[64], qFac[64], jFac[32];
    __shared__ float rowPart[4][64];

    int tid  = threadIdx.x;
    int warp = tid >> 5;
    int lane = tid & 31;

    // load kv state
#pragma unroll
    for (int i = 0; i < 4; i++) {
        int e = tid*4 + i;
        KVs[e >> 5][e & 31] = g_state[(size_t)blk*1024 + e];
    }

    for (int it = 0; it < 8; it++) {
        int ibase = it*64;
        // load Q tile (transposed) + per-row factors, zero rowPart
        for (int e = tid; e < 64*32; e += 256) {
            int rr = e >> 5, k = e & 31;
            int i = ibase + rr;
            Qst[k][rr] = (i < CH) ? g_q[(size_t)(base+i)*DM + colh + k] : 0.f;
        }
        if (tid < 64) {
            int i = ibase + tid;
            if (i < CH) {
                float scale = sqrtf(expm1f(decay*(float)(i+1)) / expm1f(decay));
                rowFac[tid] = expf(decay*(float)i) / scale;
                qFac[tid]   = expf(decay*(float)(i+1)) * lrs / scale;
            } else { rowFac[tid] = 0.f; qFac[tid] = 0.f; }
        }
        ((float*)rowPart)[tid] = 0.f;
        __syncthreads();

        float O[8];
#pragma unroll
        for (int u = 0; u < 8; u++) O[u] = 0.f;

        int maxi = ibase + 63; if (maxi > CH-1) maxi = CH-1;
        int jtiles = maxi/32 + 1;

        for (int jt = 0; jt < jtiles; jt++) {
            int jbase = jt*32;
            // load K (transposed), V, jFac
            for (int e = tid; e < 1024; e += 256) {
                int jj = e >> 5, k = e & 31;
                int j = jbase + jj;
                float kk_ = 0.f, vv_ = 0.f;
                if (j < CH) {
                    kk_ = g_k[(size_t)(base+j)*DM + colh + k];
                    vv_ = g_v[(size_t)(base+j)*DM + colh + k];
                }
                Kst[k][jj] = kk_;
                Vs[jj][k]  = vv_;
            }
            if (tid < 32) {
                int j = jbase + tid;
                jFac[tid] = (j < CH) ? expf(-decay*(float)j) : 0.f;
            }
            __syncthreads();

            // stage 1: S = Q K^T * mask ; thread -> row r=(warp&1)*32+lane, 8 jj's
            {
                int r  = ((warp & 1) << 5) + lane;
                int i  = ibase + r;
                int jb = (warp >> 1) * 8;
                float s[8];
#pragma unroll
                for (int u = 0; u < 8; u++) s[u] = 0.f;
#pragma unroll
                for (int k = 0; k < 32; k++) {
                    float qv = Qst[k][r];
                    float4 b0 = *(const float4*)&Kst[k][jb];
                    float4 b1 = *(const float4*)&Kst[k][jb+4];
                    s[0] += qv*b0.x; s[1] += qv*b0.y; s[2] += qv*b0.z; s[3] += qv*b0.w;
                    s[4] += qv*b1.x; s[5] += qv*b1.y; s[6] += qv*b1.z; s[7] += qv*b1.w;
                }
                float rf = rowFac[r];
                float part = 0.f;
#pragma unroll
                for (int u = 0; u < 8; u++) {
                    int j = jbase + jb + u;
                    float sv = s[u] * rf * jFac[jb+u];
                    if (j > i) sv = 0.f;
                    Sst[jb+u][r] = sv;
                    part += fabsf(sv);
                }
                rowPart[warp >> 1][r] += part;
            }
            __syncthreads();

            // stage 2: O += S V ; thread -> rows warp*8..+7, col=lane
#pragma unroll 8
            for (int jj = 0; jj < 32; jj++) {
                float4 a0 = *(const float4*)&Sst[jj][warp*8];
                float4 a1 = *(const float4*)&Sst[jj][warp*8+4];
                float vv = Vs[jj][lane];
                O[0] += a0.x*vv; O[1] += a0.y*vv; O[2] += a0.z*vv; O[3] += a0.w*vv;
                O[4] += a1.x*vv; O[5] += a1.y*vv; O[6] += a1.z*vv; O[7] += a1.w*vv;
            }
            __syncthreads();
        }

        // cross term: Cacc = Q @ KVstate
        float Cacc[8];
#pragma unroll
        for (int u = 0; u < 8; u++) Cacc[u] = 0.f;
#pragma unroll
        for (int k = 0; k < 32; k++) {
            float4 a0 = *(const float4*)&Qst[k][warp*8];
            float4 a1 = *(const float4*)&Qst[k][warp*8+4];
            float kvv = KVs[k][lane];
            Cacc[0] += a0.x*kvv; Cacc[1] += a0.y*kvv; Cacc[2] += a0.z*kvv; Cacc[3] += a0.w*kvv;
            Cacc[4] += a1.x*kvv; Cacc[5] += a1.y*kvv; Cacc[6] += a1.z*kvv; Cacc[7] += a1.w*kvv;
        }

        // epilogue: normalize, RMS over head dim, silu gate, store
#pragma unroll
        for (int u = 0; u < 8; u++) {
            int rr = warp*8 + u;
            int i  = ibase + rr;
            if (i < CH) {
                float rowsum = rowPart[0][rr] + rowPart[1][rr]
                             + rowPart[2][rr] + rowPart[3][rr];
                float iscale = fmaxf(rowsum, 1.f);
                float ascale = fmaxf(iscale, cs);
                float val = (O[u] + qFac[rr]*Cacc[u]) / ascale;
                float sq = warp_sum(val*val);
                val *= rsqrtf(sq*(1.f/32.f) + 1e-6f);
                size_t grow = (size_t)(base + i);
                float gv = g_g[grow*DM + colh + lane];
                float gate = gv / (1.f + expf(-gv));     // silu
                g_gate[grow*DM + colh + lane] = gate * val;
            }
        }
        __syncthreads();
    }
}

// ---------------- tiny MHA over seq=4 ; block per (b,t), warp per head ----------------
__global__ __launch_bounds__(256) void mha_kernel()
{
    int bt = blockIdx.x;            // 0..3999
    int h    = threadIdx.x >> 5;
    int lane = threadIdx.x & 31;
    size_t r0 = (size_t)bt * 4;
    float q[4], k[4], v[4];
#pragma unroll
    for (int c = 0; c < 4; c++) {
        size_t off = (r0 + c)*768 + h*KD + lane;
        q[c] = g_qkv[off] * SCALING;
        k[c] = g_qkv[off + 256];
        v[c] = g_qkv[off + 512];
    }
    float s[4][4];
#pragma unroll
    for (int i = 0; i < 4; i++)
#pragma unroll
        for (int j = 0; j < 4; j++)
            s[i][j] = warp_sum(q[i]*k[j]);
#pragma unroll
    for (int i = 0; i < 4; i++) {
        float m = fmaxf(fmaxf(s[i][0], s[i][1]), fmaxf(s[i][2], s[i][3]));
        float e0 = expf(s[i][0]-m), e1 = expf(s[i][1]-m),
              e2 = expf(s[i][2]-m), e3 = expf(s[i][3]-m);
        float inv = 1.f/(e0+e1+e2+e3);
        float o = (e0*v[0] + e1*v[1] + e2*v[2] + e3*v[3]) * inv;
        g_attn[(r0+i)*DM + h*KD + lane] = o;
    }
}

// ---------------- launcher ----------------
extern "C" void kernel_launch(void* const* d_in, const int* in_sizes, int n_in,
                              void* d_out, int out_size)
{
    const float* x    = (const float*)d_in[0];
    const float* ln1g = (const float*)d_in[1];
    const float* ln1b = (const float*)d_in[2];
    const float* ln2g = (const float*)d_in[3];
    const float* ln2b = (const float*)d_in[4];
    const float* qw   = (const float*)d_in[5];
    const float* kw   = (const float*)d_in[6];
    const float* vw   = (const float*)d_in[7];
    const float* gw   = (const float*)d_in[8];
    const float* ow   = (const float*)d_in[9];
    const float* inw  = (const float*)d_in[10];
    const float* inb  = (const float*)d_in[11];
    const float* outw = (const float*)d_in[12];
    const float* outb = (const float*)d_in[13];
    float* out = (float*)d_out;

    float *p_xn, *p_q, *p_k, *p_gate, *p_x1, *p_yn, *p_qkv, *p_attn;
    cudaGetSymbolAddress((void**)&p_xn,   g_xn);
    cudaGetSymbolAddress((void**)&p_q,    g_q);
    cudaGetSymbolAddress((void**)&p_k,    g_k);
    cudaGetSymbolAddress((void**)&p_gate, g_gate);
    cudaGetSymbolAddress((void**)&p_x1,   g_x1);
    cudaGetSymbolAddress((void**)&p_yn,   g_yn);
    cudaGetSymbolAddress((void**)&p_qkv,  g_qkv);
    cudaGetSymbolAddress((void**)&p_attn, g_attn);

    dim3 gQKVG(NROWS/128, 8);
    dim3 g256 (NROWS/128, 2);
    dim3 g768 (NROWS/128, 6);

    // stage 1: retention
    ln_kernel<<<NROWS/8, 256>>>(x, p_xn, ln1g, ln1b, 0);
    gemm_qkvg<<<gQKVG, 256>>>(p_xn, qw, kw, vw, gw);
    rotary_kernel<<<NROWS*128/256, 256>>>(p_q);
    rotary_kernel<<<NROWS*128/256, 256>>>(p_k);
    kv_kernel<<<256, 256>>>();
    scan_kernel<<<64, 256>>>();
    retention_inner<<<256, 256>>>();
    gemm_nt<<<g256, 256>>>(p_gate, ow, nullptr, x, p_x1, NROWS, DM, DM, 1.f, 0);

    // stage 2: MHA over chunk axis (permuted rows)
    ln_kernel<<<NROWS/8, 256>>>(p_x1, p_yn, ln2g, ln2b, 1);
    gemm_nt<<<g768, 256>>>(p_yn, inw, inb, nullptr, p_qkv, NROWS, 768, DM, 1.f, 0);
    mha_kernel<<<NROWS/4, 256>>>();
    gemm_nt<<<g256, 256>>>(p_attn, outw, outb, p_x1, out, NROWS, DM, DM, 1.f, 1);
}

// round 7
// speedup vs baseline: 1.8582x; 1.0838x over previous
#include <cuda_runtime.h>
#include <math.h>
#include <stdint.h>

// ---------------- problem constants ----------------
#define SEQ    2000
#define NSEQ   8            // B*C
#define NROWS  (NSEQ*SEQ)   // 16000
#define DM     256
#define NH     8
#define KD     32
#define CH     500
#define NC     4
#define SCALING 0.17677669529663689f   // 32^-0.5

// ---------------- scratch (device globals; no allocations) ----------------
__device__ float g_xn  [NROWS*DM];
__device__ float g_q   [NROWS*DM];
__device__ float g_k   [NROWS*DM];
__device__ float g_v   [NROWS*DM];
__device__ float g_g   [NROWS*DM];
__device__ float g_gate[NROWS*DM];
__device__ float g_x1  [NROWS*DM];
__device__ float g_yn  [NROWS*DM];
__device__ float g_qkv [NROWS*768];
__device__ float g_attn[NROWS*DM];
__device__ float g_kv   [256*KD*KD];
__device__ float g_state[256*KD*KD];
__device__ float g_cs   [256];

__device__ __forceinline__ float head_decay(int h) {
    return log1pf(-exp2f(-5.0f - (float)h));   // log(1 - 2^{-5-h})
}

__device__ __forceinline__ float warp_sum(float v) {
    v += __shfl_xor_sync(0xffffffffu, v, 16);
    v += __shfl_xor_sync(0xffffffffu, v, 8);
    v += __shfl_xor_sync(0xffffffffu, v, 4);
    v += __shfl_xor_sync(0xffffffffu, v, 2);
    v += __shfl_xor_sync(0xffffffffu, v, 1);
    return v;
}

// row permutation between (b,c,t) storage and (b,t,c) logical order
__device__ __forceinline__ int perm_row(int lr) {
    int b = lr / (SEQ*4);
    int rem = lr - b*(SEQ*4);
    int t = rem >> 2;
    int c = rem & 3;
    return (b*4 + c)*SEQ + t;
}

// ---------------- layernorm: one warp per row of 256 ----------------
__global__ __launch_bounds__(256) void ln_kernel(
    const float* __restrict__ src, float* __restrict__ dst,
    const float* __restrict__ gw, const float* __restrict__ bw, int permute)
{
    int row  = blockIdx.x*8 + (threadIdx.x >> 5);
    int lane = threadIdx.x & 31;
    int srow = permute ? perm_row(row) : row;

    const float* p = src + (size_t)srow*DM;
    float vals[8];
    float s = 0.f;
#pragma unroll
    for (int j = 0; j < 8; j++) { vals[j] = p[lane + 32*j]; s += vals[j]; }
    s = warp_sum(s);
    float mean = s * (1.f/256.f);
    float vs = 0.f;
#pragma unroll
    for (int j = 0; j < 8; j++) { float d = vals[j]-mean; vs += d*d; }
    vs = warp_sum(vs);
    float inv = rsqrtf(vs*(1.f/256.f) + 1e-5f);
    float* q = dst + (size_t)row*DM;
#pragma unroll
    for (int j = 0; j < 8; j++) {
        int col = lane + 32*j;
        q[col] = (vals[j]-mean)*inv*gw[col] + bw[col];
    }
}

// ================= tf32 tensor-core GEMM =================
__device__ __forceinline__ uint32_t f2tf32(float x) {
    uint32_t r; asm("cvt.rna.tf32.f32 %0, %1;" : "=r"(r) : "f"(x)); return r;
}

__device__ __forceinline__ void mma_tf32(float* d, const uint32_t* a,
                                         uint32_t b0, uint32_t b1) {
    asm volatile(
        "mma.sync.aligned.m16n8k8.row.col.f32.tf32.tf32.f32 "
        "{%0,%1,%2,%3}, {%4,%5,%6,%7}, {%8,%9}, {%0,%1,%2,%3};"
        : "+f"(d[0]), "+f"(d[1]), "+f"(d[2]), "+f"(d[3])
        : "r"(a[0]), "r"(a[1]), "r"(a[2]), "r"(a[3]), "r"(b0), "r"(b1));
}

__device__ __forceinline__ void gemm_tile(
    const float* __restrict__ A, const float* __restrict__ Wp, // Wp = W + col0*K
    const float* __restrict__ bias, const float* __restrict__ res,
    float* __restrict__ C, int K, int N, int row0, int col0,
    float alpha, int permute, uint32_t* As, uint32_t* Bs)
{
    int tid  = threadIdx.x;
    int warp = tid >> 5, lane = tid & 31;
    int wm = warp >> 1, wn = warp & 1;
    int gr = lane >> 2, gc = lane & 3;

    float acc[2][8][4];
#pragma unroll
    for (int mt = 0; mt < 2; mt++)
#pragma unroll
        for (int nt = 0; nt < 8; nt++)
#pragma unroll
            for (int u = 0; u < 4; u++) acc[mt][nt][u] = 0.f;

    float4 pa[4], pb[4];
#pragma unroll
    for (int u = 0; u < 4; u++) {
        int id = u*256 + tid;
        int m = id >> 3, kq = id & 7;
        pa[u] = *(const float4*)(A  + (size_t)(row0+m)*K + kq*4);
        pb[u] = *(const float4*)(Wp + (size_t)m*K       + kq*4);
    }

    int kblocks = K >> 5;
    for (int kb = 0; kb < kblocks; kb++) {
        __syncthreads();
#pragma unroll
        for (int u = 0; u < 4; u++) {
            int id = u*256 + tid;
            int m = id >> 3, kq = id & 7;
            uint4 av = make_uint4(f2tf32(pa[u].x), f2tf32(pa[u].y),
                                  f2tf32(pa[u].z), f2tf32(pa[u].w));
            uint4 bv = make_uint4(f2tf32(pb[u].x), f2tf32(pb[u].y),
                                  f2tf32(pb[u].z), f2tf32(pb[u].w));
            *(uint4*)&As[m*36 + kq*4] = av;
            *(uint4*)&Bs[m*36 + kq*4] = bv;
        }
        __syncthreads();
        if (kb + 1 < kblocks) {
            int koff = (kb+1)*32;
#pragma unroll
            for (int u = 0; u < 4; u++) {
                int id = u*256 + tid;
                int m = id >> 3, kq = id & 7;
                pa[u] = *(const float4*)(A  + (size_t)(row0+m)*K + koff + kq*4);
                pb[u] = *(const float4*)(Wp + (size_t)m*K       + koff + kq*4);
            }
        }
#pragma unroll
        for (int ks = 0; ks < 4; ks++) {
            int k0 = ks*8;
            uint32_t a[2][4];
#pragma unroll
            for (int mt = 0; mt < 2; mt++) {
                int base = (wm*32 + mt*16 + gr)*36 + k0 + gc;
                a[mt][0] = As[base];
                a[mt][1] = As[base + 288];     // +8 rows
                a[mt][2] = As[base + 4];
                a[mt][3] = As[base + 292];
            }
#pragma unroll
            for (int nt = 0; nt < 8; nt++) {
                int nb = (wn*64 + nt*8 + gr)*36 + k0 + gc;
                uint32_t b0 = Bs[nb], b1 = Bs[nb + 4];
                mma_tf32(acc[0][nt], a[0], b0, b1);
                mma_tf32(acc[1][nt], a[1], b0, b1);
            }
        }
    }

    // epilogue
#pragma unroll
    for (int mt = 0; mt < 2; mt++) {
#pragma unroll
        for (int h = 0; h < 2; h++) {
            int row = row0 + wm*32 + mt*16 + gr + h*8;
            int pr  = permute ? perm_row(row) : row;
            const float* rrow = res ? res + (size_t)pr*N : nullptr;
            float* crow = C + (size_t)pr*N;
#pragma unroll
            for (int nt = 0; nt < 8; nt++) {
                int c = col0 + wn*64 + nt*8 + gc*2;
                float v0 = acc[mt][nt][h*2+0] * alpha;
                float v1 = acc[mt][nt][h*2+1] * alpha;
                if (bias) { v0 += bias[c]; v1 += bias[c+1]; }
                if (rrow) { v0 += rrow[c]; v1 += rrow[c+1]; }
                *(float2*)&crow[c] = make_float2(v0, v1);
            }
        }
    }
}

__global__ __launch_bounds__(256) void gemm_nt(
    const float* __restrict__ A, const float* __restrict__ W,
    const float* __restrict__ bias, const float* __restrict__ res,
    float* __restrict__ C, int M, int N, int K, float alpha, int permute)
{
    __shared__ uint32_t As[128*36];
    __shared__ uint32_t Bs[128*36];
    int row0 = blockIdx.x * 128;
    int col0 = blockIdx.y * 128;
    gemm_tile(A, W + (size_t)col0*K, bias, res, C, K, N, row0, col0,
              alpha, permute, As, Bs);
}

// fused Q/K/V/G projections: grid (125, 8)
__global__ __launch_bounds__(256) void gemm_qkvg(const float* __restrict__ A,
    const float* __restrict__ qw, const float* __restrict__ kw,
    const float* __restrict__ vw, const float* __restrict__ gw)
{
    __shared__ uint32_t As[128*36];
    __shared__ uint32_t Bs[128*36];
    int w = blockIdx.y >> 1;
    int col0 = (blockIdx.y & 1) * 128;
    const float* W = (w == 0) ? qw : (w == 1) ? kw : (w == 2) ? vw : gw;
    float* C = (w == 0) ? g_q : (w == 1) ? g_k : (w == 2) ? g_v : g_g;
    float alpha = (w == 1) ? SCALING : 1.f;
    gemm_tile(A, W + (size_t)col0*DM, nullptr, nullptr, C, DM, DM,
              blockIdx.x*128, col0, alpha, 0, As, Bs);
}

// ---------------- rotary (theta shift) for q and k, fused ----------------
__global__ __launch_bounds__(256) void rotary2_kernel()
{
    int p = blockIdx.x*256 + threadIdx.x;       // pair index
    if (p >= NROWS*128) return;
    int row = p >> 7;
    int w   = p & 127;          // h*16 + pj
    int pj  = w & 15;
    int t   = row % SEQ;        // absolute position within sequence
    float angle = expf(-(float)pj * 0.61402269158f);  // 10000^{-pj/15}
    float sn, cn;
    sincosf((float)t * angle, &sn, &cn);
    size_t off = (size_t)row*DM + (size_t)w*2;
    float x1 = g_q[off], x2 = g_q[off+1];
    g_q[off]   = x1*cn - x2*sn;
    g_q[off+1] = x2*cn + x1*sn;
    float y1 = g_k[off], y2 = g_k[off+1];
    g_k[off]   = y1*cn - y2*sn;
    g_k[off+1] = y2*cn + y1*sn;
}

// ---------------- per-chunk kv = kr^T @ (v * vdec)  (32x32) ----------------
__global__ __launch_bounds__(256) void kv_kernel()
{
    int blk = blockIdx.x;           // b*32 + n*8 + h
    int h = blk & 7, n = (blk>>3)&3, b = blk>>5;
    int base = b*SEQ + n*CH;
    int colh = h*KD;
    float decay = head_decay(h);
    float lrs   = expm1f(500.f*decay)/expm1f(decay);   // last_row_sum

    __shared__ float Ks[32][33];
    __shared__ float Vs[32][33];
    int tid = threadIdx.x;
    int d  = tid & 31;
    int kq = tid >> 5;              // 0..7 -> rows kq*4..kq*4+3
    float acc[4] = {0.f,0.f,0.f,0.f};

    for (int jt = 0; jt < 16; jt++) {
        for (int e = tid; e < 1024; e += 256) {
            int jj = e >> 5, c = e & 31;
            int j = jt*32 + jj;
            float kk_ = 0.f, vv_ = 0.f;
            if (j < CH) {
                kk_ = g_k[(size_t)(base+j)*DM + colh + c];
                float vdec = expf(decay*(499.f - (float)j)) / lrs;
                vv_ = g_v[(size_t)(base+j)*DM + colh + c] * vdec;
            }
            Ks[jj][c] = kk_;
            Vs[jj][c] = vv_;
        }
        __syncthreads();
#pragma unroll 8
        for (int jj = 0; jj < 32; jj++) {
            float vv = Vs[jj][d];
#pragma unroll
            for (int i = 0; i < 4; i++)
                acc[i] += Ks[jj][kq*4+i] * vv;
        }
        __syncthreads();
    }
#pragma unroll
    for (int i = 0; i < 4; i++)
        g_kv[(size_t)blk*1024 + (kq*4+i)*32 + d] = acc[i];
}

// ---------------- sequential scan over chunks per (b,h) ----------------
__global__ __launch_bounds__(256) void scan_kernel()
{
    int bh = blockIdx.x;            // b*8 + h
    int b = bh >> 3, h = bh & 7;
    float decay = head_decay(h);
    float cross_decay = expf(decay * 500.f);
    int tid = threadIdx.x;
    int d  = tid & 31;
    int kq = tid >> 5;
    float st[4] = {0.f,0.f,0.f,0.f};
    float cs = 1.f;
    __shared__ float part[8][32];
    __shared__ float csh;

    for (int n = 0; n < NC; n++) {
        int idx = b*32 + n*8 + h;
#pragma unroll
        for (int i = 0; i < 4; i++)
            g_state[(size_t)idx*1024 + (kq*4+i)*32 + d] = st[i];
        if (tid == 0) g_cs[idx] = cs;
        float colp = 0.f;
#pragma unroll
        for (int i = 0; i < 4; i++) {
            st[i] = st[i]*cross_decay + g_kv[(size_t)idx*1024 + (kq*4+i)*32 + d];
            colp += fabsf(st[i]);
        }
        part[kq][d] = colp;
        __syncthreads();
        if (tid < 32) {
            float c = 0.f;
#pragma unroll
            for (int q = 0; q < 8; q++) c += part[q][tid];
            for (int off = 16; off; off >>= 1)
                c = fmaxf(c, __shfl_xor_sync(0xffffffffu, c, off));
            if (tid == 0) csh = fmaxf(c, 1.f);
        }
        __syncthreads();
        cs = csh;
    }
}

// ---------------- tensor-core retention inner + cross + RMS + gate ----------------
// block per (b,n,h,i-tile): 2048 blocks, 256 threads = 8 warps (4x2 warp grid)
__global__ __launch_bounds__(256) void retention_tc()
{
    int blk = blockIdx.x & 255;          // b*32 + n*8 + h
    int it  = 7 - (blockIdx.x >> 8);     // longest tiles first
    int h = blk & 7, n = (blk>>3)&3, b = blk>>5;
    int base = b*SEQ + n*CH;
    int colh = h*KD;
    float decay = head_decay(h);
    float lrs   = expm1f(500.f*decay)/expm1f(decay);
    float cs    = g_cs[blk];
    int i0 = it*64;

    __shared__ uint32_t Qs [64*36];      // tf32 Q (row i, k)
    __shared__ uint32_t Ks [32*36];      // tf32 K (row j, k)
    __shared__ uint32_t Vt [32*36];      // tf32 V transposed (d, j)
    __shared__ uint32_t Ss [64*36];      // tf32 S (i, j-local); reused as fp32 out
    __shared__ uint32_t StT[32*36];      // tf32 state transposed (d, k)
    __shared__ float rowFac[64], qFacS[64], jFacT[32];
    __shared__ float rowAcc[2][64];

    int tid  = threadIdx.x;
    int warp = tid >> 5, lane = tid & 31;
    int wm = warp >> 1, wn = warp & 1;
    int gr = lane >> 2, gc = lane & 3;

    // load Q i-tile (tf32)
#pragma unroll
    for (int u = 0; u < 2; u++) {
        int idx = tid + 256*u;
        int r = idx >> 3, kq = (idx & 7)*4;
        int i = i0 + r;
        float4 qv = make_float4(0.f,0.f,0.f,0.f);
        if (i < CH) qv = *(const float4*)&g_q[(size_t)(base+i)*DM + colh + kq];
        Qs[r*36+kq+0] = f2tf32(qv.x); Qs[r*36+kq+1] = f2tf32(qv.y);
        Qs[r*36+kq+2] = f2tf32(qv.z); Qs[r*36+kq+3] = f2tf32(qv.w);
    }
    // load state transposed (tf32)
#pragma unroll
    for (int u = 0; u < 4; u++) {
        int e = tid + 256*u;            // e = k*32 + d
        int k = e >> 5, d = e & 31;
        StT[d*36 + k] = f2tf32(g_state[(size_t)blk*1024 + e]);
    }
    // per-row factors
    if (tid < 64) {
        int i = i0 + tid;
        if (i < CH) {
            float scale = sqrtf(expm1f(decay*(float)(i+1)) / expm1f(decay));
            rowFac[tid] = expf(decay*(float)i) / scale;
            qFacS[tid]  = expf(decay*(float)(i+1)) * lrs / scale;
        } else { rowFac[tid] = 0.f; qFacS[tid] = 0.f; }
    }
    if (tid < 128) rowAcc[tid >> 6][tid & 63] = 0.f;
    __syncthreads();

    // cross term: Cacc = Q @ state
    float cacc[2][4] = {{0.f,0.f,0.f,0.f},{0.f,0.f,0.f,0.f}};
    float oacc[2][4] = {{0.f,0.f,0.f,0.f},{0.f,0.f,0.f,0.f}};
    {
        uint32_t a[4];
#pragma unroll
        for (int ks = 0; ks < 4; ks++) {
            int k0 = ks*8;
            a[0] = Qs[(wm*16+gr)*36   + k0+gc];
            a[1] = Qs[(wm*16+8+gr)*36 + k0+gc];
            a[2] = Qs[(wm*16+gr)*36   + k0+gc+4];
            a[3] = Qs[(wm*16+8+gr)*36 + k0+gc+4];
#pragma unroll
            for (int nt = 0; nt < 2; nt++) {
                int d = wn*16 + nt*8 + gr;
                mma_tf32(cacc[nt], a, StT[d*36+k0+gc], StT[d*36+k0+gc+4]);
            }
        }
    }

    int imax = i0 + 63; if (imax > CH-1) imax = CH-1;
    int njt = (imax >> 5) + 1;

    for (int jt = 0; jt < njt; jt++) {
        int j0 = jt*32;
        __syncthreads();
        // load K tile + V tile (transposed), tf32
        {
            int r = tid >> 3, kq = (tid & 7)*4;
            int j = j0 + r;
            float4 kk = make_float4(0.f,0.f,0.f,0.f), vv = kk;
            if (j < CH) {
                kk = *(const float4*)&g_k[(size_t)(base+j)*DM + colh + kq];
                vv = *(const float4*)&g_v[(size_t)(base+j)*DM + colh + kq];
            }
            Ks[r*36+kq+0] = f2tf32(kk.x); Ks[r*36+kq+1] = f2tf32(kk.y);
            Ks[r*36+kq+2] = f2tf32(kk.z); Ks[r*36+kq+3] = f2tf32(kk.w);
            Vt[(kq+0)*36+r] = f2tf32(vv.x); Vt[(kq+1)*36+r] = f2tf32(vv.y);
            Vt[(kq+2)*36+r] = f2tf32(vv.z); Vt[(kq+3)*36+r] = f2tf32(vv.w);
        }
        if (tid < 32) {
            int j = j0 + tid;
            jFacT[tid] = (j < CH) ? expf(-decay*(float)j) : 0.f;
        }
        __syncthreads();

        // stage 1: S = Q K^T (tensor), then factors + mask + |S| rowsum
        float sacc[2][4] = {{0.f,0.f,0.f,0.f},{0.f,0.f,0.f,0.f}};
        {
            uint32_t a[4];
#pragma unroll
            for (int ks = 0; ks < 4; ks++) {
                int k0 = ks*8;
                a[0] = Qs[(wm*16+gr)*36   + k0+gc];
                a[1] = Qs[(wm*16+8+gr)*36 + k0+gc];
                a[2] = Qs[(wm*16+gr)*36   + k0+gc+4];
                a[3] = Qs[(wm*16+8+gr)*36 + k0+gc+4];
#pragma unroll
                for (int nt = 0; nt < 2; nt++) {
                    int j = wn*16 + nt*8 + gr;
                    mma_tf32(sacc[nt], a, Ks[j*36+k0+gc], Ks[j*36+k0+gc+4]);
                }
            }
        }
        {
            int rl = wm*16 + gr;
            int ig0 = i0 + rl, ig1 = ig0 + 8;
            float rf0 = rowFac[rl], rf1 = rowFac[rl+8];
            float p0 = 0.f, p1 = 0.f;
#pragma unroll
            for (int nt = 0; nt < 2; nt++) {
                int c0 = wn*16 + nt*8 + 2*gc;
                int jg = j0 + c0;
                float jf0 = jFacT[c0], jf1 = jFacT[c0+1];
                float s00 = (jg   <= ig0) ? sacc[nt][0]*rf0*jf0 : 0.f;
                float s01 = (jg+1 <= ig0) ? sacc[nt][1]*rf0*jf1 : 0.f;
                float s10 = (jg   <= ig1) ? sacc[nt][2]*rf1*jf0 : 0.f;
                float s11 = (jg+1 <= ig1) ? sacc[nt][3]*rf1*jf1 : 0.f;
                p0 += fabsf(s00) + fabsf(s01);
                p1 += fabsf(s10) + fabsf(s11);
                Ss[rl*36     + c0]   = f2tf32(s00);
                Ss[rl*36     + c0+1] = f2tf32(s01);
                Ss[(rl+8)*36 + c0]   = f2tf32(s10);
                Ss[(rl+8)*36 + c0+1] = f2tf32(s11);
            }
            p0 += __shfl_xor_sync(0xffffffffu, p0, 1);
            p0 += __shfl_xor_sync(0xffffffffu, p0, 2);
            p1 += __shfl_xor_sync(0xffffffffu, p1, 1);
            p1 += __shfl_xor_sync(0xffffffffu, p1, 2);
            if (gc == 0) {
                rowAcc[wn][rl]   += p0;
                rowAcc[wn][rl+8] += p1;
            }
        }
        __syncthreads();

        // stage 2: O += S V (tensor)
        {
            uint32_t a[4];
#pragma unroll
            for (int ks = 0; ks < 4; ks++) {
                int k0 = ks*8;
                a[0] = Ss[(wm*16+gr)*36   + k0+gc];
                a[1] = Ss[(wm*16+8+gr)*36 + k0+gc];
                a[2] = Ss[(wm*16+gr)*36   + k0+gc+4];
                a[3] = Ss[(wm*16+8+gr)*36 + k0+gc+4];
#pragma unroll
                for (int nt = 0; nt < 2; nt++) {
                    int d = wn*16 + nt*8 + gr;
                    mma_tf32(oacc[nt], a, Vt[d*36+k0+gc], Vt[d*36+k0+gc+4]);
                }
            }
        }
    }

    // epilogue part 1: combine inner+cross, scale, stage to smem
    __syncthreads();
    float* OutS = (float*)Ss;
    {
        int rl = wm*16 + gr;
        float rs0 = rowAcc[0][rl]   + rowAcc[1][rl];
        float rs1 = rowAcc[0][rl+8] + rowAcc[1][rl+8];
        float as0 = fmaxf(fmaxf(rs0, 1.f), cs);
        float as1 = fmaxf(fmaxf(rs1, 1.f), cs);
        float qf0 = qFacS[rl], qf1 = qFacS[rl+8];
#pragma unroll
        for (int nt = 0; nt < 2; nt++) {
            int d0 = wn*16 + nt*8 + 2*gc;
            OutS[rl*36     + d0]   = (oacc[nt][0] + qf0*cacc[nt][0]) / as0;
            OutS[rl*36     + d0+1] = (oacc[nt][1] + qf0*cacc[nt][1]) / as0;
            OutS[(rl+8)*36 + d0]   = (oacc[nt][2] + qf1*cacc[nt][2]) / as1;
            OutS[(rl+8)*36 + d0+1] = (oacc[nt][3] + qf1*cacc[nt][3]) / as1;
        }
    }
    __syncthreads();

    // epilogue part 2: RMS over head dim + silu gate + store
#pragma unroll
    for (int u = 0; u < 8; u++) {
        int rl = warp*8 + u;
        int i  = i0 + rl;
        if (i < CH) {
            float v = OutS[rl*36 + lane];
            float sq = warp_sum(v*v);
            v *= rsqrtf(sq*(1.f/32.f) + 1e-6f);
            size_t grow = (size_t)(base + i);
            float gv = g_g[grow*DM + colh + lane];
            float gate = gv / (1.f + expf(-gv));     // silu
            g_gate[grow*DM + colh + lane] = gate * v;
        }
    }
}

// ---------------- tiny MHA over seq=4 ; block per (b,t), warp per head ----------------
__global__ __launch_bounds__(256) void mha_kernel()
{
    int bt = blockIdx.x;            // 0..3999
    int h    = threadIdx.x >> 5;
    int lane = threadIdx.x & 31;
    size_t r0 = (size_t)bt * 4;
    float q[4], k[4], v[4];
#pragma unroll
    for (int c = 0; c < 4; c++) {
        size_t off = (r0 + c)*768 + h*KD + lane;
        q[c] = g_qkv[off] * SCALING;
        k[c] = g_qkv[off + 256];
        v[c] = g_qkv[off + 512];
    }
    float s[4][4];
#pragma unroll
    for (int i = 0; i < 4; i++)
#pragma unroll
        for (int j = 0; j < 4; j++)
            s[i][j] = warp_sum(q[i]*k[j]);
#pragma unroll
    for (int i = 0; i < 4; i++) {
        float m = fmaxf(fmaxf(s[i][0], s[i][1]), fmaxf(s[i][2], s[i][3]));
        float e0 = expf(s[i][0]-m), e1 = expf(s[i][1]-m),
              e2 = expf(s[i][2]-m), e3 = expf(s[i][3]-m);
        float inv = 1.f/(e0+e1+e2+e3);
        float o = (e0*v[0] + e1*v[1] + e2*v[2] + e3*v[3]) * inv;
        g_attn[(r0+i)*DM + h*KD + lane] = o;
    }
}

// ---------------- launcher ----------------
extern "C" void kernel_launch(void* const* d_in, const int* in_sizes, int n_in,
                              void* d_out, int out_size)
{
    const float* x    = (const float*)d_in[0];
    const float* ln1g = (const float*)d_in[1];
    const float* ln1b = (const float*)d_in[2];
    const float* ln2g = (const float*)d_in[3];
    const float* ln2b = (const float*)d_in[4];
    const float* qw   = (const float*)d_in[5];
    const float* kw   = (const float*)d_in[6];
    const float* vw   = (const float*)d_in[7];
    const float* gw   = (const float*)d_in[8];
    const float* ow   = (const float*)d_in[9];
    const float* inw  = (const float*)d_in[10];
    const float* inb  = (const float*)d_in[11];
    const float* outw = (const float*)d_in[12];
    const float* outb = (const float*)d_in[13];
    float* out = (float*)d_out;

    float *p_xn, *p_gate, *p_x1, *p_yn, *p_qkv, *p_attn;
    cudaGetSymbolAddress((void**)&p_xn,   g_xn);
    cudaGetSymbolAddress((void**)&p_gate, g_gate);
    cudaGetSymbolAddress((void**)&p_x1,   g_x1);
    cudaGetSymbolAddress((void**)&p_yn,   g_yn);
    cudaGetSymbolAddress((void**)&p_qkv,  g_qkv);
    cudaGetSymbolAddress((void**)&p_attn, g_attn);

    dim3 gQKVG(NROWS/128, 8);
    dim3 g256 (NROWS/128, 2);
    dim3 g768 (NROWS/128, 6);

    // stage 1: retention
    ln_kernel<<<NROWS/8, 256>>>(x, p_xn, ln1g, ln1b, 0);
    gemm_qkvg<<<gQKVG, 256>>>(p_xn, qw, kw, vw, gw);
    rotary2_kernel<<<NROWS*128/256, 256>>>();
    kv_kernel<<<256, 256>>>();
    scan_kernel<<<64, 256>>>();
    retention_tc<<<2048, 256>>>();
    gemm_nt<<<g256, 256>>>(p_gate, ow, nullptr, x, p_x1, NROWS, DM, DM, 1.f, 0);

    // stage 2: MHA over chunk axis (permuted rows)
    ln_kernel<<<NROWS/8, 256>>>(p_x1, p_yn, ln2g, ln2b, 1);
    gemm_nt<<<g768, 256>>>(p_yn, inw, inb, nullptr, p_qkv, NROWS, 768, DM, 1.f, 0);
    mha_kernel<<<NROWS/4, 256>>>();
    gemm_nt<<<g256, 256>>>(p_attn, outw, outb, p_x1, out, NROWS, DM, DM, 1.f, 1);
}

// round 11
// speedup vs baseline: 2.9049x; 1.5633x over previous
#include <cuda_runtime.h>
#include <math.h>
#include <stdint.h>

// ---------------- problem constants ----------------
#define SEQ    2000
#define NSEQ   8            // B*C
#define NROWS  (NSEQ*SEQ)   // 16000
#define DM     256
#define NH     8
#define KD     32
#define CH     500
#define NC     4
#define SCALING 0.17677669529663689f   // 32^-0.5

// ---------------- scratch (device globals; no allocations) ----------------
__device__ float g_xn  [NROWS*DM];
__device__ float g_q   [NROWS*DM];
__device__ float g_k   [NROWS*DM];
__device__ float g_v   [NROWS*DM];
__device__ float g_g   [NROWS*DM];
__device__ float g_gate[NROWS*DM];
__device__ float g_x1  [NROWS*DM];
__device__ float g_yn  [NROWS*DM];
__device__ float g_qkv [NROWS*768];
__device__ float g_attn[NROWS*DM];
__device__ float g_kvp  [1024*KD*KD];   // 4 partial segments per (b,n,h)
__device__ float g_state[256*KD*KD];
__device__ float g_cs   [256];

__device__ __forceinline__ float head_decay(int h) {
    return log1pf(-exp2f(-5.0f - (float)h));   // log(1 - 2^{-5-h})
}

__device__ __forceinline__ float warp_sum(float v) {
    v += __shfl_xor_sync(0xffffffffu, v, 16);
    v += __shfl_xor_sync(0xffffffffu, v, 8);
    v += __shfl_xor_sync(0xffffffffu, v, 4);
    v += __shfl_xor_sync(0xffffffffu, v, 2);
    v += __shfl_xor_sync(0xffffffffu, v, 1);
    return v;
}

// row permutation between (b,c,t) storage and (b,t,c) logical order
__device__ __forceinline__ int perm_row(int lr) {
    int b = lr / (SEQ*4);
    int rem = lr - b*(SEQ*4);
    int t = rem >> 2;
    int c = rem & 3;
    return (b*4 + c)*SEQ + t;
}

// ---------------- layernorm: one warp per row of 256 ----------------
__global__ __launch_bounds__(256) void ln_kernel(
    const float* __restrict__ src, float* __restrict__ dst,
    const float* __restrict__ gw, const float* __restrict__ bw, int permute)
{
    int row  = blockIdx.x*8 + (threadIdx.x >> 5);
    int lane = threadIdx.x & 31;
    int srow = permute ? perm_row(row) : row;

    const float* p = src + (size_t)srow*DM;
    float vals[8];
    float s = 0.f;
#pragma unroll
    for (int j = 0; j < 8; j++) { vals[j] = p[lane + 32*j]; s += vals[j]; }
    s = warp_sum(s);
    float mean = s * (1.f/256.f);
    float vs = 0.f;
#pragma unroll
    for (int j = 0; j < 8; j++) { float d = vals[j]-mean; vs += d*d; }
    vs = warp_sum(vs);
    float inv = rsqrtf(vs*(1.f/256.f) + 1e-5f);
    float* q = dst + (size_t)row*DM;
#pragma unroll
    for (int j = 0; j < 8; j++) {
        int col = lane + 32*j;
        q[col] = (vals[j]-mean)*inv*gw[col] + bw[col];
    }
}

// ================= tf32 tensor-core GEMM =================
__device__ __forceinline__ uint32_t f2tf32(float x) {
    uint32_t r; asm("cvt.rna.tf32.f32 %0, %1;" : "=r"(r) : "f"(x)); return r;
}

__device__ __forceinline__ void mma_tf32(float* d, const uint32_t* a,
                                         uint32_t b0, uint32_t b1) {
    asm volatile(
        "mma.sync.aligned.m16n8k8.row.col.f32.tf32.tf32.f32 "
        "{%0,%1,%2,%3}, {%4,%5,%6,%7}, {%8,%9}, {%0,%1,%2,%3};"
        : "+f"(d[0]), "+f"(d[1]), "+f"(d[2]), "+f"(d[3])
        : "r"(a[0]), "r"(a[1]), "r"(a[2]), "r"(a[3]), "r"(b0), "r"(b1));
}

// rot: apply rotary (theta-shift) to the output pair (v0,v1) at column c, row t
__device__ __forceinline__ void gemm_tile(
    const float* __restrict__ A, const float* __restrict__ Wp, // Wp = W + col0*K
    const float* __restrict__ bias, const float* __restrict__ res,
    float* __restrict__ C, int K, int N, int row0, int col0,
    float alpha, int permute, int rot, uint32_t* As, uint32_t* Bs)
{
    int tid  = threadIdx.x;
    int warp = tid >> 5, lane = tid & 31;
    int wm = warp >> 1, wn = warp & 1;
    int gr = lane >> 2, gc = lane & 3;

    float acc[2][8][4];
#pragma unroll
    for (int mt = 0; mt < 2; mt++)
#pragma unroll
        for (int nt = 0; nt < 8; nt++)
#pragma unroll
            for (int u = 0; u < 4; u++) acc[mt][nt][u] = 0.f;

    float4 pa[4], pb[4];
#pragma unroll
    for (int u = 0; u < 4; u++) {
        int id = u*256 + tid;
        int m = id >> 3, kq = id & 7;
        pa[u] = *(const float4*)(A  + (size_t)(row0+m)*K + kq*4);
        pb[u] = *(const float4*)(Wp + (size_t)m*K       + kq*4);
    }

    int kblocks = K >> 5;
    for (int kb = 0; kb < kblocks; kb++) {
        __syncthreads();
#pragma unroll
        for (int u = 0; u < 4; u++) {
            int id = u*256 + tid;
            int m = id >> 3, kq = id & 7;
            uint4 av = make_uint4(f2tf32(pa[u].x), f2tf32(pa[u].y),
                                  f2tf32(pa[u].z), f2tf32(pa[u].w));
            uint4 bv = make_uint4(f2tf32(pb[u].x), f2tf32(pb[u].y),
                                  f2tf32(pb[u].z), f2tf32(pb[u].w));
            *(uint4*)&As[m*36 + kq*4] = av;
            *(uint4*)&Bs[m*36 + kq*4] = bv;
        }
        __syncthreads();
        if (kb + 1 < kblocks) {
            int koff = (kb+1)*32;
#pragma unroll
            for (int u = 0; u < 4; u++) {
                int id = u*256 + tid;
                int m = id >> 3, kq = id & 7;
                pa[u] = *(const float4*)(A  + (size_t)(row0+m)*K + koff + kq*4);
                pb[u] = *(const float4*)(Wp + (size_t)m*K       + koff + kq*4);
            }
        }
#pragma unroll
        for (int ks = 0; ks < 4; ks++) {
            int k0 = ks*8;
            uint32_t a[2][4];
#pragma unroll
            for (int mt = 0; mt < 2; mt++) {
                int base = (wm*32 + mt*16 + gr)*36 + k0 + gc;
                a[mt][0] = As[base];
                a[mt][1] = As[base + 288];     // +8 rows
                a[mt][2] = As[base + 4];
                a[mt][3] = As[base + 292];
            }
#pragma unroll
            for (int nt = 0; nt < 8; nt++) {
                int nb = (wn*64 + nt*8 + gr)*36 + k0 + gc;
                uint32_t b0 = Bs[nb], b1 = Bs[nb + 4];
                mma_tf32(acc[0][nt], a[0], b0, b1);
                mma_tf32(acc[1][nt], a[1], b0, b1);
            }
        }
    }

    // epilogue
#pragma unroll
    for (int mt = 0; mt < 2; mt++) {
#pragma unroll
        for (int h = 0; h < 2; h++) {
            int row = row0 + wm*32 + mt*16 + gr + h*8;
            int pr  = permute ? perm_row(row) : row;
            const float* rrow = res ? res + (size_t)pr*N : nullptr;
            float* crow = C + (size_t)pr*N;
            int t = row % SEQ;     // only used when rot
#pragma unroll
            for (int nt = 0; nt < 8; nt++) {
                int c = col0 + wn*64 + nt*8 + gc*2;
                float v0 = acc[mt][nt][h*2+0] * alpha;
                float v1 = acc[mt][nt][h*2+1] * alpha;
                if (bias) { v0 += bias[c]; v1 += bias[c+1]; }
                if (rrow) { v0 += rrow[c]; v1 += rrow[c+1]; }
                if (rot) {
                    int pj = (c >> 1) & 15;
                    float angle = expf(-(float)pj * 0.61402269158f);
                    float sn, cn;
                    sincosf((float)t * angle, &sn, &cn);
                    float r0 = v0*cn - v1*sn;
                    float r1 = v1*cn + v0*sn;
                    v0 = r0; v1 = r1;
                }
                *(float2*)&crow[c] = make_float2(v0, v1);
            }
        }
    }
}

__global__ __launch_bounds__(256) void gemm_nt(
    const float* __restrict__ A, const float* __restrict__ W,
    const float* __restrict__ bias, const float* __restrict__ res,
    float* __restrict__ C, int M, int N, int K, float alpha, int permute)
{
    __shared__ uint32_t As[128*36];
    __shared__ uint32_t Bs[128*36];
    int row0 = blockIdx.x * 128;
    int col0 = blockIdx.y * 128;
    gemm_tile(A, W + (size_t)col0*K, bias, res, C, K, N, row0, col0,
              alpha, permute, 0, As, Bs);
}

// fused Q/K/V/G projections: grid (125, 8); rotary fused for q,k outputs
__global__ __launch_bounds__(256) void gemm_qkvg(const float* __restrict__ A,
    const float* __restrict__ qw, const float* __restrict__ kw,
    const float* __restrict__ vw, const float* __restrict__ gw)
{
    __shared__ uint32_t As[128*36];
    __shared__ uint32_t Bs[128*36];
    int w = blockIdx.y >> 1;
    int col0 = (blockIdx.y & 1) * 128;
    const float* W = (w == 0) ? qw : (w == 1) ? kw : (w == 2) ? vw : gw;
    float* C = (w == 0) ? g_q : (w == 1) ? g_k : (w == 2) ? g_v : g_g;
    float alpha = (w == 1) ? SCALING : 1.f;
    int rot = (w <= 1) ? 1 : 0;
    gemm_tile(A, W + (size_t)col0*DM, nullptr, nullptr, C, DM, DM,
              blockIdx.x*128, col0, alpha, 0, rot, As, Bs);
}

// ---------------- per-chunk kv partials: grid 1024 = 256 x 4 segments ----------
// segment s covers j in [s*125, s*125+125)
__global__ __launch_bounds__(256) void kv_kernel()
{
    int blk = blockIdx.x & 255;      // b*32 + n*8 + h
    int seg = blockIdx.x >> 8;       // 0..3
    int h = blk & 7, n = (blk>>3)&3, b = blk>>5;
    int base = b*SEQ + n*CH;
    int colh = h*KD;
    int j0s = seg*125;
    float decay = head_decay(h);
    float lrs   = expm1f(500.f*decay)/expm1f(decay);   // last_row_sum

    __shared__ float Ks[32][33];
    __shared__ float Vs[32][33];
    int tid = threadIdx.x;
    int d  = tid & 31;
    int kq = tid >> 5;              // 0..7 -> rows kq*4..kq*4+3
    float acc[4] = {0.f,0.f,0.f,0.f};

    for (int jt = 0; jt < 4; jt++) {
        for (int e = tid; e < 1024; e += 256) {
            int jj = e >> 5, c = e & 31;
            int jl = jt*32 + jj;
            float kk_ = 0.f, vv_ = 0.f;
            if (jl < 125) {
                int j = j0s + jl;
                kk_ = g_k[(size_t)(base+j)*DM + colh + c];
                float vdec = expf(decay*(499.f - (float)j)) / lrs;
                vv_ = g_v[(size_t)(base+j)*DM + colh + c] * vdec;
            }
            Ks[jj][c] = kk_;
            Vs[jj][c] = vv_;
        }
        __syncthreads();
#pragma unroll 8
        for (int jj = 0; jj < 32; jj++) {
            float vv = Vs[jj][d];
#pragma unroll
            for (int i = 0; i < 4; i++)
                acc[i] += Ks[jj][kq*4+i] * vv;
        }
        __syncthreads();
    }
#pragma unroll
    for (int i = 0; i < 4; i++)
        g_kvp[(size_t)(blk*4+seg)*1024 + (kq*4+i)*32 + d] = acc[i];
}

// ---------------- sequential scan over chunks per (b,h) ----------------
__global__ __launch_bounds__(256) void scan_kernel()
{
    int bh = blockIdx.x;            // b*8 + h
    int b = bh >> 3, h = bh & 7;
    float decay = head_decay(h);
    float cross_decay = expf(decay * 500.f);
    int tid = threadIdx.x;
    int d  = tid & 31;
    int kq = tid >> 5;
    float st[4] = {0.f,0.f,0.f,0.f};
    float cs = 1.f;
    __shared__ float part[8][32];
    __shared__ float csh;

    for (int n = 0; n < NC; n++) {
        int idx = b*32 + n*8 + h;
#pragma unroll
        for (int i = 0; i < 4; i++)
            g_state[(size_t)idx*1024 + (kq*4+i)*32 + d] = st[i];
        if (tid == 0) g_cs[idx] = cs;
        float colp = 0.f;
#pragma unroll
        for (int i = 0; i < 4; i++) {
            int off = (kq*4+i)*32 + d;
            float kvsum = g_kvp[(size_t)(idx*4+0)*1024 + off]
                        + g_kvp[(size_t)(idx*4+1)*1024 + off]
                        + g_kvp[(size_t)(idx*4+2)*1024 + off]
                        + g_kvp[(size_t)(idx*4+3)*1024 + off];
            st[i] = st[i]*cross_decay + kvsum;
            colp += fabsf(st[i]);
        }
        part[kq][d] = colp;
        __syncthreads();
        if (tid < 32) {
            float c = 0.f;
#pragma unroll
            for (int q = 0; q < 8; q++) c += part[q][tid];
            for (int off = 16; off; off >>= 1)
                c = fmaxf(c, __shfl_xor_sync(0xffffffffu, c, off));
            if (tid == 0) csh = fmaxf(c, 1.f);
        }
        __syncthreads();
        cs = csh;
    }
}

// ---------------- tensor-core retention inner + cross + RMS + gate ----------------
// block per (b,n,h,i-tile): 2048 blocks, 256 threads = 8 warps (4x2 warp grid)
__global__ __launch_bounds__(256) void retention_tc()
{
    int blk = blockIdx.x & 255;          // b*32 + n*8 + h
    int it  = 7 - (blockIdx.x >> 8);     // longest tiles first
    int h = blk & 7, n = (blk>>3)&3, b = blk>>5;
    int base = b*SEQ + n*CH;
    int colh = h*KD;
    float decay = head_decay(h);
    float lrs   = expm1f(500.f*decay)/expm1f(decay);
    float cs    = g_cs[blk];
    int i0 = it*64;

    __shared__ uint32_t Qs [64*36];      // tf32 Q (row i, k)
    __shared__ uint32_t Ks [32*36];      // tf32 K (row j, k)
    __shared__ uint32_t Vt [32*36];      // tf32 V transposed (d, j)
    __shared__ uint32_t Ss [64*36];      // tf32 S (i, j-local); reused as fp32 out
    __shared__ uint32_t StT[32*36];      // tf32 state transposed (d, k)
    __shared__ float rowFac[64], qFacS[64], jFacT[32];
    __shared__ float rowAcc[2][64];

    int tid  = threadIdx.x;
    int warp = tid >> 5, lane = tid & 31;
    int wm = warp >> 1, wn = warp & 1;
    int gr = lane >> 2, gc = lane & 3;

    // load Q i-tile (tf32)
#pragma unroll
    for (int u = 0; u < 2; u++) {
        int idx = tid + 256*u;
        int r = idx >> 3, kq = (idx & 7)*4;
        int i = i0 + r;
        float4 qv = make_float4(0.f,0.f,0.f,0.f);
        if (i < CH) qv = *(const float4*)&g_q[(size_t)(base+i)*DM + colh + kq];
        Qs[r*36+kq+0] = f2tf32(qv.x); Qs[r*36+kq+1] = f2tf32(qv.y);
        Qs[r*36+kq+2] = f2tf32(qv.z); Qs[r*36+kq+3] = f2tf32(qv.w);
    }
    // load state transposed (tf32)
#pragma unroll
    for (int u = 0; u < 4; u++) {
        int e = tid + 256*u;            // e = k*32 + d
        int k = e >> 5, d = e & 31;
        StT[d*36 + k] = f2tf32(g_state[(size_t)blk*1024 + e]);
    }
    // per-row factors
    if (tid < 64) {
        int i = i0 + tid;
        if (i < CH) {
            float scale = sqrtf(expm1f(decay*(float)(i+1)) / expm1f(decay));
            rowFac[tid] = expf(decay*(float)i) / scale;
            qFacS[tid]  = expf(decay*(float)(i+1)) * lrs / scale;
        } else { rowFac[tid] = 0.f; qFacS[tid] = 0.f; }
    }
    if (tid < 128) rowAcc[tid >> 6][tid & 63] = 0.f;
    __syncthreads();

    // cross term: Cacc = Q @ state
    float cacc[2][4] = {{0.f,0.f,0.f,0.f},{0.f,0.f,0.f,0.f}};
    float oacc[2][4] = {{0.f,0.f,0.f,0.f},{0.f,0.f,0.f,0.f}};
    {
        uint32_t a[4];
#pragma unroll
        for (int ks = 0; ks < 4; ks++) {
            int k0 = ks*8;
            a[0] = Qs[(wm*16+gr)*36   + k0+gc];
            a[1] = Qs[(wm*16+8+gr)*36 + k0+gc];
            a[2] = Qs[(wm*16+gr)*36   + k0+gc+4];
            a[3] = Qs[(wm*16+8+gr)*36 + k0+gc+4];
#pragma unroll
            for (int nt = 0; nt < 2; nt++) {
                int d = wn*16 + nt*8 + gr;
                mma_tf32(cacc[nt], a, StT[d*36+k0+gc], StT[d*36+k0+gc+4]);
            }
        }
    }

    int imax = i0 + 63; if (imax > CH-1) imax = CH-1;
    int njt = (imax >> 5) + 1;

    for (int jt = 0; jt < njt; jt++) {
        int j0 = jt*32;
        __syncthreads();
        // load K tile + V tile (transposed), tf32
        {
            int r = tid >> 3, kq = (tid & 7)*4;
            int j = j0 + r;
            float4 kk = make_float4(0.f,0.f,0.f,0.f), vv = kk;
            if (j < CH) {
                kk = *(const float4*)&g_k[(size_t)(base+j)*DM + colh + kq];
                vv = *(const float4*)&g_v[(size_t)(base+j)*DM + colh + kq];
            }
            Ks[r*36+kq+0] = f2tf32(kk.x); Ks[r*36+kq+1] = f2tf32(kk.y);
            Ks[r*36+kq+2] = f2tf32(kk.z); Ks[r*36+kq+3] = f2tf32(kk.w);
            Vt[(kq+0)*36+r] = f2tf32(vv.x); Vt[(kq+1)*36+r] = f2tf32(vv.y);
            Vt[(kq+2)*36+r] = f2tf32(vv.z); Vt[(kq+3)*36+r] = f2tf32(vv.w);
        }
        if (tid < 32) {
            int j = j0 + tid;
            jFacT[tid] = (j < CH) ? expf(-decay*(float)j) : 0.f;
        }
        __syncthreads();

        // stage 1: S = Q K^T (tensor), then factors + mask + |S| rowsum
        float sacc[2][4] = {{0.f,0.f,0.f,0.f},{0.f,0.f,0.f,0.f}};
        {
            uint32_t a[4];
#pragma unroll
            for (int ks = 0; ks < 4; ks++) {
                int k0 = ks*8;
                a[0] = Qs[(wm*16+gr)*36   + k0+gc];
                a[1] = Qs[(wm*16+8+gr)*36 + k0+gc];
                a[2] = Qs[(wm*16+gr)*36   + k0+gc+4];
                a[3] = Qs[(wm*16+8+gr)*36 + k0+gc+4];
#pragma unroll
                for (int nt = 0; nt < 2; nt++) {
                    int j = wn*16 + nt*8 + gr;
                    mma_tf32(sacc[nt], a, Ks[j*36+k0+gc], Ks[j*36+k0+gc+4]);
                }
            }
        }
        {
            int rl = wm*16 + gr;
            int ig0 = i0 + rl, ig1 = ig0 + 8;
            float rf0 = rowFac[rl], rf1 = rowFac[rl+8];
            float p0 = 0.f, p1 = 0.f;
#pragma unroll
            for (int nt = 0; nt < 2; nt++) {
                int c0 = wn*16 + nt*8 + 2*gc;
                int jg = j0 + c0;
                float jf0 = jFacT[c0], jf1 = jFacT[c0+1];
                float s00 = (jg   <= ig0) ? sacc[nt][0]*rf0*jf0 : 0.f;
                float s01 = (jg+1 <= ig0) ? sacc[nt][1]*rf0*jf1 : 0.f;
                float s10 = (jg   <= ig1) ? sacc[nt][2]*rf1*jf0 : 0.f;
                float s11 = (jg+1 <= ig1) ? sacc[nt][3]*rf1*jf1 : 0.f;
                p0 += fabsf(s00) + fabsf(s01);
                p1 += fabsf(s10) + fabsf(s11);
                Ss[rl*36     + c0]   = f2tf32(s00);
                Ss[rl*36     + c0+1] = f2tf32(s01);
                Ss[(rl+8)*36 + c0]   = f2tf32(s10);
                Ss[(rl+8)*36 + c0+1] = f2tf32(s11);
            }
            p0 += __shfl_xor_sync(0xffffffffu, p0, 1);
            p0 += __shfl_xor_sync(0xffffffffu, p0, 2);
            p1 += __shfl_xor_sync(0xffffffffu, p1, 1);
            p1 += __shfl_xor_sync(0xffffffffu, p1, 2);
            if (gc == 0) {
                rowAcc[wn][rl]   += p0;
                rowAcc[wn][rl+8] += p1;
            }
        }
        __syncthreads();

        // stage 2: O += S V (tensor)
        {
            uint32_t a[4];
#pragma unroll
            for (int ks = 0; ks < 4; ks++) {
                int k0 = ks*8;
                a[0] = Ss[(wm*16+gr)*36   + k0+gc];
                a[1] = Ss[(wm*16+8+gr)*36 + k0+gc];
                a[2] = Ss[(wm*16+gr)*36   + k0+gc+4];
                a[3] = Ss[(wm*16+8+gr)*36 + k0+gc+4];
#pragma unroll
                for (int nt = 0; nt < 2; nt++) {
                    int d = wn*16 + nt*8 + gr;
                    mma_tf32(oacc[nt], a, Vt[d*36+k0+gc], Vt[d*36+k0+gc+4]);
                }
            }
        }
    }

    // epilogue part 1: combine inner+cross, scale, stage to smem
    __syncthreads();
    float* OutS = (float*)Ss;
    {
        int rl = wm*16 + gr;
        float rs0 = rowAcc[0][rl]   + rowAcc[1][rl];
        float rs1 = rowAcc[0][rl+8] + rowAcc[1][rl+8];
        float as0 = fmaxf(fmaxf(rs0, 1.f), cs);
        float as1 = fmaxf(fmaxf(rs1, 1.f), cs);
        float qf0 = qFacS[rl], qf1 = qFacS[rl+8];
#pragma unroll
        for (int nt = 0; nt < 2; nt++) {
            int d0 = wn*16 + nt*8 + 2*gc;
            OutS[rl*36     + d0]   = (oacc[nt][0] + qf0*cacc[nt][0]) / as0;
            OutS[rl*36     + d0+1] = (oacc[nt][1] + qf0*cacc[nt][1]) / as0;
            OutS[(rl+8)*36 + d0]   = (oacc[nt][2] + qf1*cacc[nt][2]) / as1;
            OutS[(rl+8)*36 + d0+1] = (oacc[nt][3] + qf1*cacc[nt][3]) / as1;
        }
    }
    __syncthreads();

    // epilogue part 2: RMS over head dim + silu gate + store
#pragma unroll
    for (int u = 0; u < 8; u++) {
        int rl = warp*8 + u;
        int i  = i0 + rl;
        if (i < CH) {
            float v = OutS[rl*36 + lane];
            float sq = warp_sum(v*v);
            v *= rsqrtf(sq*(1.f/32.f) + 1e-6f);
            size_t grow = (size_t)(base + i);
            float gv = g_g[grow*DM + colh + lane];
            float gate = gv / (1.f + expf(-gv));     // silu
            g_gate[grow*DM + colh + lane] = gate * v;
        }
    }
}

// ---------------- tiny MHA over seq=4 ; block per (b,t), warp per head ----------------
__global__ __launch_bounds__(256) void mha_kernel()
{
    int bt = blockIdx.x;            // 0..3999
    int h    = threadIdx.x >> 5;
    int lane = threadIdx.x & 31;
    size_t r0 = (size_t)bt * 4;
    float q[4], k[4], v[4];
#pragma unroll
    for (int c = 0; c < 4; c++) {
        size_t off = (r0 + c)*768 + h*KD + lane;
        q[c] = g_qkv[off] * SCALING;
        k[c] = g_qkv[off + 256];
        v[c] = g_qkv[off + 512];
    }
    float s[4][4];
#pragma unroll
    for (int i = 0; i < 4; i++)
#pragma unroll
        for (int j = 0; j < 4; j++)
            s[i][j] = warp_sum(q[i]*k[j]);
#pragma unroll
    for (int i = 0; i < 4; i++) {
        float m = fmaxf(fmaxf(s[i][0], s[i][1]), fmaxf(s[i][2], s[i][3]));
        float e0 = expf(s[i][0]-m), e1 = expf(s[i][1]-m),
              e2 = expf(s[i][2]-m), e3 = expf(s[i][3]-m);
        float inv = 1.f/(e0+e1+e2+e3);
        float o = (e0*v[0] + e1*v[1] + e2*v[2] + e3*v[3]) * inv;
        g_attn[(r0+i)*DM + h*KD + lane] = o;
    }
}

// ---------------- launcher ----------------
extern "C" void kernel_launch(void* const* d_in, const int* in_sizes, int n_in,
                              void* d_out, int out_size)
{
    const float* x    = (const float*)d_in[0];
    const float* ln1g = (const float*)d_in[1];
    const float* ln1b = (const float*)d_in[2];
    const float* ln2g = (const float*)d_in[3];
    const float* ln2b = (const float*)d_in[4];
    const float* qw   = (const float*)d_in[5];
    const float* kw   = (const float*)d_in[6];
    const float* vw   = (const float*)d_in[7];
    const float* gw   = (const float*)d_in[8];
    const float* ow   = (const float*)d_in[9];
    const float* inw  = (const float*)d_in[10];
    const float* inb  = (const float*)d_in[11];
    const float* outw = (const float*)d_in[12];
    const float* outb = (const float*)d_in[13];
    float* out = (float*)d_out;

    float *p_xn, *p_gate, *p_x1, *p_yn, *p_qkv, *p_attn;
    cudaGetSymbolAddress((void**)&p_xn,   g_xn);
    cudaGetSymbolAddress((void**)&p_gate, g_gate);
    cudaGetSymbolAddress((void**)&p_x1,   g_x1);
    cudaGetSymbolAddress((void**)&p_yn,   g_yn);
    cudaGetSymbolAddress((void**)&p_qkv,  g_qkv);
    cudaGetSymbolAddress((void**)&p_attn, g_attn);

    dim3 gQKVG(NROWS/128, 8);
    dim3 g256 (NROWS/128, 2);
    dim3 g768 (NROWS/128, 6);

    // stage 1: retention
    ln_kernel<<<NROWS/8, 256>>>(x, p_xn, ln1g, ln1b, 0);
    gemm_qkvg<<<gQKVG, 256>>>(p_xn, qw, kw, vw, gw);
    kv_kernel<<<1024, 256>>>();
    scan_kernel<<<64, 256>>>();
    retention_tc<<<2048, 256>>>();
    gemm_nt<<<g256, 256>>>(p_gate, ow, nullptr, x, p_x1, NROWS, DM, DM, 1.f, 0);

    // stage 2: MHA over chunk axis (permuted rows)
    ln_kernel<<<NROWS/8, 256>>>(p_x1, p_yn, ln2g, ln2b, 1);
    gemm_nt<<<g768, 256>>>(p_yn, inw, inb, nullptr, p_qkv, NROWS, 768, DM, 1.f, 0);
    mha_kernel<<<NROWS/4, 256>>>();
    gemm_nt<<<g256, 256>>>(p_attn, outw, outb, p_x1, out, NROWS, DM, DM, 1.f, 1);
}